// round 7
// baseline (speedup 1.0000x reference)
#include <cuda_runtime.h>
#include <cuda_fp16.h>
#include <cuda_bf16.h>
#include <cstdint>

// ---------------- problem constants ----------------
#define NND   50000
#define DEG   16
#define IN_F  128
#define HID   64
#define NH    4
#define BATCH 64

// ---------------- scratch ----------------
__device__ __half g_f1h[NND*NH*HID];
__device__ float  g_el1[NND*NH];
__device__ float  g_er1[NND*NH];
__device__ float  g_h1 [NND*NH*HID];
__device__ __half g_f2h[NND*HID];
__device__ float  g_el2[NND];
__device__ float  g_er2[NND];
__device__ float  g_h2 [NND*HID];
__device__ float  g_loss[BATCH];
// W as [n][k] bf16 hi/lo (dense, k contiguous)
__device__ __nv_bfloat16 g_w1hi[(NH*HID)*IN_F];
__device__ __nv_bfloat16 g_w1lo[(NH*HID)*IN_F];
__device__ __nv_bfloat16 g_w2hi[HID*(NH*HID)];
__device__ __nv_bfloat16 g_w2lo[HID*(NH*HID)];

__device__ __forceinline__ uint32_t smem_u32(const void* p) {
    uint32_t a;
    asm("{ .reg .u64 t; cvta.to.shared.u64 t, %1; cvt.u32.u64 %0, t; }"
        : "=r"(a) : "l"(p));
    return a;
}
__device__ __forceinline__ void ldmatrix_x4(uint32_t& r0, uint32_t& r1,
                                            uint32_t& r2, uint32_t& r3, uint32_t addr) {
    asm volatile("ldmatrix.sync.aligned.m8n8.x4.shared.b16 {%0,%1,%2,%3}, [%4];"
        : "=r"(r0), "=r"(r1), "=r"(r2), "=r"(r3) : "r"(addr));
}
__device__ __forceinline__ void mma_bf16(float* c, const uint32_t* a,
                                         uint32_t b0, uint32_t b1) {
    asm volatile("mma.sync.aligned.m16n8k16.row.col.f32.bf16.bf16.f32 "
        "{%0,%1,%2,%3}, {%4,%5,%6,%7}, {%8,%9}, {%0,%1,%2,%3};"
        : "+f"(c[0]), "+f"(c[1]), "+f"(c[2]), "+f"(c[3])
        : "r"(a[0]), "r"(a[1]), "r"(a[2]), "r"(a[3]), "r"(b0), "r"(b1));
}
__device__ __forceinline__ void split_bf16(float x, unsigned short& hi, unsigned short& lo) {
    __nv_bfloat16 bh = __float2bfloat16(x);
    __nv_bfloat16 bl = __float2bfloat16(x - __bfloat162float(bh));
    hi = *reinterpret_cast<unsigned short*>(&bh);
    lo = *reinterpret_cast<unsigned short*>(&bl);
}

// ---------------- prep: W fp32 [k][n] -> bf16 hi/lo [n][k] ----------------
__global__ void prep_w(const float* __restrict__ W, __nv_bfloat16* __restrict__ hi,
                       __nv_bfloat16* __restrict__ lo, int K, int N) {
    int idx = blockIdx.x*blockDim.x + threadIdx.x;
    if (idx >= N*K) return;
    int n = idx / K, k = idx - n*K;
    unsigned short h, l;
    split_bf16(W[k*N + n], h, l);
    hi[idx] = *reinterpret_cast<__nv_bfloat16*>(&h);
    lo[idx] = *reinterpret_cast<__nv_bfloat16*>(&l);
}

// ------- split-bf16 tensor-core GEMM (mma.sync) + fused el/er + fp16 out -------
// D[m,n] = A[gidx[m],:] @ W[:,n];  W given as [n][k] bf16 hi/lo.
// Warp tile: WTM x 64.  3 passes: Ahi*Bhi + Ahi*Blo + Alo*Bhi.
template<int K, int N, int WM, int WN, int WTM>
__global__ __launch_bounds__(32*WM*WN, 1)
void gat_gemm_mma(const float* __restrict__ A, const int* __restrict__ gidx,
                  const __nv_bfloat16* __restrict__ Bhi, const __nv_bfloat16* __restrict__ Blo,
                  const float* __restrict__ al, const float* __restrict__ ar,
                  __half* __restrict__ Ch, float* __restrict__ el, float* __restrict__ er,
                  int M) {
    constexpr int NT  = 32*WM*WN;
    constexpr int BM  = WM*WTM;
    constexpr int MF  = WTM/16;          // m-frags per warp
    constexpr int NHh = N/64;
    constexpr int SA  = K + 8;           // padded strides (bf16 units)
    constexpr int SB  = K + 8;
    constexpr int ASZ = BM*SA*2;         // bytes, one A buffer
    constexpr int BSZ = N*SB*2;
    constexpr int KS  = K/16;
    extern __shared__ char smem[];
    char* sAhi = smem;
    char* sAlo = smem + ASZ;
    char* sBhi = smem + 2*ASZ;
    char* sBlo = smem + 2*ASZ + BSZ;

    const int tid  = threadIdx.x;
    const int warp = tid >> 5, lane = tid & 31;
    const int wm = warp % WM, wn = warp / WM;
    const int m0 = blockIdx.x * BM;

    // ---- gather + convert A block to bf16 hi/lo smem ----
    for (int idx = tid; idx < BM*(K/4); idx += NT) {
        int m  = idx / (K/4);
        int kq = idx - m*(K/4);
        int gm = m0 + m;
        int row = (gm < M) ? (gidx ? gidx[gm] : gm) : (gidx ? gidx[M-1] : M-1);
        float4 v = reinterpret_cast<const float4*>(A + (long)row*K)[kq];
        unsigned short h0,h1,h2,h3,l0,l1,l2,l3;
        split_bf16(v.x, h0, l0); split_bf16(v.y, h1, l1);
        split_bf16(v.z, h2, l2); split_bf16(v.w, h3, l3);
        uint2 uh = make_uint2((uint32_t)h0 | ((uint32_t)h1<<16),
                              (uint32_t)h2 | ((uint32_t)h3<<16));
        uint2 ul = make_uint2((uint32_t)l0 | ((uint32_t)l1<<16),
                              (uint32_t)l2 | ((uint32_t)l3<<16));
        *reinterpret_cast<uint2*>(sAhi + (m*SA + kq*4)*2) = uh;
        *reinterpret_cast<uint2*>(sAlo + (m*SA + kq*4)*2) = ul;
    }
    // ---- copy W tiles (dense [n][k]) into padded smem ----
    for (int idx = tid; idx < N*(K/8); idx += NT) {
        int n = idx / (K/8);
        int q = idx - n*(K/8);
        uint4 vh = reinterpret_cast<const uint4*>(Bhi)[(long)n*(K/8) + q];
        uint4 vl = reinterpret_cast<const uint4*>(Blo)[(long)n*(K/8) + q];
        *reinterpret_cast<uint4*>(sBhi + (n*SB + q*8)*2) = vh;
        *reinterpret_cast<uint4*>(sBlo + (n*SB + q*8)*2) = vl;
    }
    __syncthreads();

    // ---- ldmatrix lane addressing (row = i&15, col-half = i>>4) ----
    const int lrow = lane & 15, lcol = (lane >> 4) * 8;
    uint32_t aBase[MF], bBase[4];
    #pragma unroll
    for (int f = 0; f < MF; f++)
        aBase[f] = smem_u32(sAhi) + ((wm*WTM + f*16 + lrow)*SA + lcol)*2;
    #pragma unroll
    for (int nb = 0; nb < 4; nb++)
        bBase[nb] = smem_u32(sBhi) + ((wn*64 + nb*16 + lrow)*SB + lcol)*2;

    float acc[MF][8][4];
    #pragma unroll
    for (int f = 0; f < MF; f++)
        #pragma unroll
        for (int nf = 0; nf < 8; nf++)
            #pragma unroll
            for (int q = 0; q < 4; q++) acc[f][nf][q] = 0.f;

    // ---- 3 passes: (Ahi,Bhi) (Ahi,Blo) (Alo,Bhi) ----
    #pragma unroll
    for (int p = 0; p < 3; p++) {
        const uint32_t aoff = (p == 2) ? (uint32_t)ASZ : 0u;
        const uint32_t boff = (p == 1) ? (uint32_t)BSZ : 0u;
        #pragma unroll
        for (int s = 0; s < KS; s++) {
            uint32_t a[MF][4];
            #pragma unroll
            for (int f = 0; f < MF; f++)
                ldmatrix_x4(a[f][0], a[f][1], a[f][2], a[f][3],
                            aBase[f] + aoff + s*32);
            uint32_t b[4][4];
            #pragma unroll
            for (int nb = 0; nb < 4; nb++)
                ldmatrix_x4(b[nb][0], b[nb][1], b[nb][2], b[nb][3],
                            bBase[nb] + boff + s*32);
            #pragma unroll
            for (int f = 0; f < MF; f++)
                #pragma unroll
                for (int nf = 0; nf < 8; nf++)
                    mma_bf16(acc[f][nf], a[f],
                             b[nf>>1][nf&1], b[nf>>1][2 + (nf&1)]);
        }
        __syncwarp();
    }

    // ---- epilogue: fp16 store + fused el/er (quad reduce) ----
    const int t = lane & 3, g = lane >> 2;
    float al0[8], al1[8], ar0[8], ar1[8];
    #pragma unroll
    for (int nf = 0; nf < 8; nf++) {
        int n = wn*64 + nf*8 + 2*t;
        al0[nf] = al[n]; al1[nf] = al[n+1];
        ar0[nf] = ar[n]; ar1[nf] = ar[n+1];
    }
    #pragma unroll
    for (int f = 0; f < MF; f++) {
        int gmA = m0 + wm*WTM + f*16 + g;
        int gmB = gmA + 8;
        float slA=0.f, srA=0.f, slB=0.f, srB=0.f;
        #pragma unroll
        for (int nf = 0; nf < 8; nf++) {
            slA += acc[f][nf][0]*al0[nf] + acc[f][nf][1]*al1[nf];
            srA += acc[f][nf][0]*ar0[nf] + acc[f][nf][1]*ar1[nf];
            slB += acc[f][nf][2]*al0[nf] + acc[f][nf][3]*al1[nf];
            srB += acc[f][nf][2]*ar0[nf] + acc[f][nf][3]*ar1[nf];
            int n = wn*64 + nf*8 + 2*t;
            if (gmA < M) {
                __half2 h = __floats2half2_rn(acc[f][nf][0], acc[f][nf][1]);
                *reinterpret_cast<__half2*>(Ch + (long)gmA*N + n) = h;
            }
            if (gmB < M) {
                __half2 h = __floats2half2_rn(acc[f][nf][2], acc[f][nf][3]);
                *reinterpret_cast<__half2*>(Ch + (long)gmB*N + n) = h;
            }
        }
        #pragma unroll
        for (int o = 1; o < 4; o <<= 1) {
            slA += __shfl_xor_sync(~0u, slA, o);
            srA += __shfl_xor_sync(~0u, srA, o);
            slB += __shfl_xor_sync(~0u, slB, o);
            srB += __shfl_xor_sync(~0u, srB, o);
        }
        if (t == 0) {
            if (gmA < M) { el[(long)gmA*NHh + wn] = slA; er[(long)gmA*NHh + wn] = srA; }
            if (gmB < M) { el[(long)gmB*NHh + wn] = slB; er[(long)gmB*NHh + wn] = srB; }
        }
    }
}

// ------------- segment-softmax + fp16 weighted aggregation -----------------
template<int NHh, bool RELU>
__global__ void agg_kernel(const __half* __restrict__ f, const float* __restrict__ el,
                           const float* __restrict__ er, const float* __restrict__ bias,
                           const int* __restrict__ src, float* __restrict__ out) {
    int gw   = (blockIdx.x * blockDim.x + threadIdx.x) >> 5;
    int lane = threadIdx.x & 31;
    if (gw >= NND * NHh) return;
    int v = gw / NHh, h = gw - v*NHh;

    float erv = er[v*NHh + h];
    int   off = 0;
    float e   = -1e30f;
    if (lane < DEG) {
        int s = src[v * DEG + lane];
        off = s * (NHh*HID*2);
        float x = el[s*NHh + h] + erv;
        e = x > 0.f ? x : 0.2f * x;            // leaky_relu(0.2)
    }
    float m = e;
    #pragma unroll
    for (int o = 8; o > 0; o >>= 1) m = fmaxf(m, __shfl_xor_sync(~0u, m, o, 16));
    float ex = (lane < DEG) ? __expf(e - m) : 0.f;
    float sm = ex;
    #pragma unroll
    for (int o = 8; o > 0; o >>= 1) sm += __shfl_xor_sync(~0u, sm, o, 16);
    float alpha = ex / sm;

    int half_ = lane >> 4;
    int dl    = lane & 15;
    const char* base = reinterpret_cast<const char*>(f) + h*(HID*2) + dl*8;
    float4 acc = make_float4(0.f, 0.f, 0.f, 0.f);
    #pragma unroll
    for (int j = 0; j < DEG/2; j++) {
        int   eidx = 2*j + half_;
        int   oj = __shfl_sync(~0u, off,   eidx);
        float aj = __shfl_sync(~0u, alpha, eidx);
        uint2 raw = *reinterpret_cast<const uint2*>(base + oj);
        float2 f0 = __half22float2(*reinterpret_cast<__half2*>(&raw.x));
        float2 f1 = __half22float2(*reinterpret_cast<__half2*>(&raw.y));
        acc.x += aj * f0.x;
        acc.y += aj * f0.y;
        acc.z += aj * f1.x;
        acc.w += aj * f1.y;
    }
    acc.x += __shfl_xor_sync(~0u, acc.x, 16);
    acc.y += __shfl_xor_sync(~0u, acc.y, 16);
    acc.z += __shfl_xor_sync(~0u, acc.z, 16);
    acc.w += __shfl_xor_sync(~0u, acc.w, 16);
    if (half_ == 0) {
        int d = dl * 4;
        float4 b4 = *reinterpret_cast<const float4*>(&bias[h*HID + d]);
        float4 o4 = make_float4(acc.x + b4.x, acc.y + b4.y, acc.z + b4.z, acc.w + b4.w);
        if (RELU) {
            o4.x = fmaxf(o4.x, 0.f); o4.y = fmaxf(o4.y, 0.f);
            o4.z = fmaxf(o4.z, 0.f); o4.w = fmaxf(o4.w, 0.f);
        }
        *reinterpret_cast<float4*>(&out[((long)v * NHh + h) * HID + d]) = o4;
    }
}

// ---------------- scores, labels, per-row loss ----------------
__global__ void score_kernel(const float* __restrict__ h2, const int* __restrict__ uid,
                             const int* __restrict__ iid, float* __restrict__ out) {
    int i = blockIdx.x;
    int d = threadIdx.x;
    float su = h2[(long)uid[i] * HID + d];
    float si = h2[(long)iid[i] * HID + d];
    float sc = su * si;
    out[1 + i*BATCH + d] = sc;
    out[1 + BATCH*BATCH + i*BATCH + d] = (i == d) ? 1.f : 0.f;

    __shared__ float buf[BATCH];
    __shared__ float diag;
    if (d == i) diag = sc;
    buf[d] = sc;
    __syncthreads();
    for (int st = 32; st > 0; st >>= 1) {
        if (d < st) buf[d] = fmaxf(buf[d], buf[d + st]);
        __syncthreads();
    }
    float mx = buf[0];
    __syncthreads();
    buf[d] = expf(sc - mx);
    __syncthreads();
    for (int st = 32; st > 0; st >>= 1) {
        if (d < st) buf[d] += buf[d + st];
        __syncthreads();
    }
    if (d == 0) {
        float lse = mx + logf(buf[0]);
        g_loss[i] = lse - diag;
    }
}

__global__ void finalize_kernel(float* __restrict__ out) {
    if (threadIdx.x == 0) {
        float s = 0.f;
        for (int i = 0; i < BATCH; i++) s += g_loss[i];
        out[0] = s / (float)BATCH;
    }
}

// ---------------- launcher ----------------
extern "C" void kernel_launch(void* const* d_in, const int* in_sizes, int n_in,
                              void* d_out, int out_size) {
    const int*   feat_ids = (const int*)  d_in[0];
    const int*   src      = (const int*)  d_in[1];
    const int*   user_ids = (const int*)  d_in[3];
    const int*   item_ids = (const int*)  d_in[4];
    const float* emb      = (const float*)d_in[5];
    const float* W1       = (const float*)d_in[6];
    const float* a_l1     = (const float*)d_in[7];
    const float* a_r1     = (const float*)d_in[8];
    const float* b1       = (const float*)d_in[9];
    const float* W2       = (const float*)d_in[10];
    const float* a_l2     = (const float*)d_in[11];
    const float* a_r2     = (const float*)d_in[12];
    const float* b2       = (const float*)d_in[13];
    float* out = (float*)d_out;

    __half *f1h, *f2h;
    float *el1, *er1, *h1, *el2, *er2, *h2;
    __nv_bfloat16 *w1hi, *w1lo, *w2hi, *w2lo;
    cudaGetSymbolAddress((void**)&f1h,  g_f1h);
    cudaGetSymbolAddress((void**)&el1,  g_el1);
    cudaGetSymbolAddress((void**)&er1,  g_er1);
    cudaGetSymbolAddress((void**)&h1,   g_h1);
    cudaGetSymbolAddress((void**)&f2h,  g_f2h);
    cudaGetSymbolAddress((void**)&el2,  g_el2);
    cudaGetSymbolAddress((void**)&er2,  g_er2);
    cudaGetSymbolAddress((void**)&h2,   g_h2);
    cudaGetSymbolAddress((void**)&w1hi, g_w1hi);
    cudaGetSymbolAddress((void**)&w1lo, g_w1lo);
    cudaGetSymbolAddress((void**)&w2hi, g_w2hi);
    cudaGetSymbolAddress((void**)&w2lo, g_w2lo);

    // GEMM1: K=128, N=256, 8 warps (WM=2 x WN=4), warp tile 64x64, BM=128
    // smem = 2*(128*136*2) + 2*(256*136*2) = 208,896 B
    constexpr int SM1 = 2*(128*(IN_F+8)*2) + 2*(256*(IN_F+8)*2);
    // GEMM2: K=256, N=64, 4 warps (WM=4 x WN=1), warp tile 32x64, BM=128
    constexpr int SM2 = 2*(128*(NH*HID+8)*2) + 2*(64*(NH*HID+8)*2);
    cudaFuncSetAttribute((const void*)gat_gemm_mma<IN_F,NH*HID,2,4,64>,
                         cudaFuncAttributeMaxDynamicSharedMemorySize, SM1);
    cudaFuncSetAttribute((const void*)gat_gemm_mma<NH*HID,HID,4,1,32>,
                         cudaFuncAttributeMaxDynamicSharedMemorySize, SM2);

    // W -> bf16 hi/lo [n][k]
    prep_w<<<(IN_F*NH*HID + 255)/256, 256>>>(W1, w1hi, w1lo, IN_F, NH*HID);
    prep_w<<<(NH*HID*HID + 255)/256, 256>>>(W2, w2hi, w2lo, NH*HID, HID);

    const int GRID = (NND + 127)/128;   // 391

    // layer 1: f1 = emb[feat_ids] @ W1 (50000x128x256), fused el1/er1, fp16 out
    gat_gemm_mma<IN_F,NH*HID,2,4,64><<<GRID, 256, SM1>>>(
        emb, feat_ids, w1hi, w1lo, a_l1, a_r1, f1h, el1, er1, NND);
    agg_kernel<NH,true><<<(NND*NH)/8, 256>>>(f1h, el1, er1, b1, src, h1);

    // layer 2: f2 = h1 @ W2 (50000x256x64), fused el2/er2, fp16 out
    gat_gemm_mma<NH*HID,HID,4,1,32><<<GRID, 128, SM2>>>(
        h1, nullptr, w2hi, w2lo, a_l2, a_r2, f2h, el2, er2, NND);
    agg_kernel<1,false><<<NND/8, 256>>>(f2h, el2, er2, b2, src, h2);

    score_kernel<<<BATCH, BATCH>>>(h2, user_ids, item_ids, out);
    finalize_kernel<<<1, 32>>>(out);
}

// round 8
// speedup vs baseline: 1.2730x; 1.2730x over previous
#include <cuda_runtime.h>
#include <cuda_fp16.h>

// ---------------- problem constants ----------------
#define NND   50000
#define DEG   16
#define IN_F  128
#define HID   64
#define NH    4
#define BATCH 64

typedef unsigned long long ull;

// ---------------- scratch ----------------
__device__ __half g_f1h[NND*NH*HID];
__device__ float  g_el1[NND*NH];
__device__ float  g_er1[NND*NH];
__device__ float  g_h1 [NND*NH*HID];
__device__ __half g_f2h[NND*HID];
__device__ float  g_el2[NND];
__device__ float  g_er2[NND];
__device__ float  g_h2 [NND*HID];
__device__ float  g_loss[BATCH];

// ---------------- packed f32x2 helpers ----------------
__device__ __forceinline__ ull pack_dup(float x) {
    ull r; asm("mov.b64 %0, {%1, %1};" : "=l"(r) : "f"(x)); return r;
}
__device__ __forceinline__ void ffma2(ull& acc, ull a, ull b) {
    asm("fma.rn.f32x2 %0, %1, %2, %0;" : "+l"(acc) : "l"(a), "l"(b));
}
__device__ __forceinline__ float2 unpack2(ull v) {
    float2 f; asm("mov.b64 {%0, %1}, %2;" : "=f"(f.x), "=f"(f.y) : "l"(v)); return f;
}

// ---------------- GEMM with 2-D warp tiling + fused attention dots ----------
// Ch[m, 0:BN] = half(A[gidx[m], :] @ B) ; el/er[m,h] = fp32 head dots
// Warp tile = 32(M) x 64(N); lanes = 4(M) x 8(N); thread tile 8x8.
template<int BM,int BN,int BK,int NHh>
__global__ __launch_bounds__((BM/8)*(BN/8))
void gemm_fused(const float* __restrict__ A, const int* __restrict__ gidx,
                const float* __restrict__ B,
                const float* __restrict__ al, const float* __restrict__ ar,
                __half* __restrict__ Ch, float* __restrict__ el, float* __restrict__ er,
                int M, int K) {
    constexpr int TM = 8, TN = 8;
    constexpr int NT = (BM/TM)*(BN/TN);
    constexpr int NWARP = NT/32;
    constexpr int WN = BN/64;
    constexpr int WM = NWARP/WN;
    static_assert(WM*32 == BM && WN*64 == BN, "warp tiling");
    __shared__ float As[BK][BM];
    __shared__ float Bs[BK][BN];
    const int tid  = threadIdx.x;
    const int warp = tid >> 5;
    const int lane = tid & 31;
    const int wm = warp % WM, wn = warp / WM;
    const int lr = lane >> 3, lc = lane & 7;
    const int ty = wm*4 + lr;
    const int tx = wn*8 + lc;
    const int m0 = blockIdx.x * BM;

    constexpr int A_F4 = BM*BK/4;
    constexpr int A_IT = A_F4 / NT;
    static_assert(A_IT >= 1 && A_F4 % NT == 0, "A tiling");
    long arow[A_IT];
    #pragma unroll
    for (int r = 0; r < A_IT; r++) {
        int idx = tid + r*NT;
        int mA  = idx / (BK/4);
        int gm  = m0 + mA;
        int row = (gm < M) ? (gidx ? gidx[gm] : gm) : 0;
        arow[r] = (long)row * K;
    }
    constexpr int B_F4 = BK*BN/4;
    constexpr int B_IT = B_F4 / NT;
    static_assert(B_IT >= 1 && B_F4 % NT == 0, "B tiling");

    ull acc2[TM/2][TN];
    #pragma unroll
    for (int i = 0; i < TM/2; i++)
        #pragma unroll
        for (int j = 0; j < TN; j++) acc2[i][j] = 0ull;

    for (int k0 = 0; k0 < K; k0 += BK) {
        #pragma unroll
        for (int r = 0; r < A_IT; r++) {
            int idx = tid + r*NT;
            int mA  = idx / (BK/4);
            int kq  = idx % (BK/4);
            float4 v = *reinterpret_cast<const float4*>(A + arow[r] + k0 + kq*4);
            As[kq*4+0][mA] = v.x;
            As[kq*4+1][mA] = v.y;
            As[kq*4+2][mA] = v.z;
            As[kq*4+3][mA] = v.w;
        }
        #pragma unroll
        for (int r = 0; r < B_IT; r++) {
            int idx = tid + r*NT;
            int kB  = idx / (BN/4);
            int nq  = idx % (BN/4);
            float4 v = *reinterpret_cast<const float4*>(B + (long)(k0+kB)*BN + nq*4);
            *reinterpret_cast<float4*>(&Bs[kB][nq*4]) = v;
        }
        __syncthreads();
        #pragma unroll
        for (int k = 0; k < BK; k++) {
            ull a2[TM/2];
            const ull* ap = reinterpret_cast<const ull*>(&As[k][ty*TM]);
            #pragma unroll
            for (int i = 0; i < TM/2; i++) a2[i] = ap[i];
            float4 blo = *reinterpret_cast<const float4*>(&Bs[k][tx*TN]);
            float4 bhi = *reinterpret_cast<const float4*>(&Bs[k][tx*TN+4]);
            ull b2[TN];
            b2[0]=pack_dup(blo.x); b2[1]=pack_dup(blo.y);
            b2[2]=pack_dup(blo.z); b2[3]=pack_dup(blo.w);
            b2[4]=pack_dup(bhi.x); b2[5]=pack_dup(bhi.y);
            b2[6]=pack_dup(bhi.z); b2[7]=pack_dup(bhi.w);
            #pragma unroll
            for (int i = 0; i < TM/2; i++)
                #pragma unroll
                for (int j = 0; j < TN; j++) ffma2(acc2[i][j], a2[i], b2[j]);
        }
        __syncthreads();
    }

    float acc[TM][TN];
    #pragma unroll
    for (int i = 0; i < TM/2; i++)
        #pragma unroll
        for (int j = 0; j < TN; j++) {
            float2 p = unpack2(acc2[i][j]);
            acc[2*i  ][j] = p.x;
            acc[2*i+1][j] = p.y;
        }

    float alr[TN], arr[TN];
    #pragma unroll
    for (int j = 0; j < TN; j++) { int n = tx*TN + j; alr[j] = al[n]; arr[j] = ar[n]; }

    #pragma unroll
    for (int i = 0; i < TM; i++) {
        int gm = m0 + ty*TM + i;
        float sl = 0.f, sr = 0.f;
        #pragma unroll
        for (int j = 0; j < TN; j++) { sl += acc[i][j]*alr[j]; sr += acc[i][j]*arr[j]; }
        #pragma unroll
        for (int o = 1; o < 8; o <<= 1) {
            sl += __shfl_xor_sync(~0u, sl, o);
            sr += __shfl_xor_sync(~0u, sr, o);
        }
        if (gm < M) {
            __half2 p0 = __floats2half2_rn(acc[i][0], acc[i][1]);
            __half2 p1 = __floats2half2_rn(acc[i][2], acc[i][3]);
            __half2 p2 = __floats2half2_rn(acc[i][4], acc[i][5]);
            __half2 p3 = __floats2half2_rn(acc[i][6], acc[i][7]);
            uint4 w;
            w.x = *reinterpret_cast<unsigned*>(&p0);
            w.y = *reinterpret_cast<unsigned*>(&p1);
            w.z = *reinterpret_cast<unsigned*>(&p2);
            w.w = *reinterpret_cast<unsigned*>(&p3);
            *reinterpret_cast<uint4*>(&Ch[(long)gm*BN + tx*TN]) = w;
            if (lc == 0) {
                el[(long)gm*NHh + wn] = sl;
                er[(long)gm*NHh + wn] = sr;
            }
        }
    }
}

// -------- layer-1 aggregation: ONE warp per node, all 4 heads --------
// lanes encode (edge 0..7, head 0..3); each lane also handles edge+8.
// Gather: 16 iters, one LDG.128 per lane (16B slice of the 512B row).
__global__ void agg4_kernel(const __half* __restrict__ f, const float* __restrict__ el,
                            const float* __restrict__ er, const float* __restrict__ bias,
                            const int* __restrict__ src, float* __restrict__ out) {
    int v    = (blockIdx.x * blockDim.x + threadIdx.x) >> 5;
    int lane = threadIdx.x & 31;
    if (v >= NND) return;
    const int h    = lane & 3;
    const int eidx = lane >> 2;              // edge 0..7

    float erv = er[v*NH + h];
    int s0 = src[v*DEG + eidx];
    int s1 = src[v*DEG + eidx + 8];
    float x0 = el[s0*NH + h] + erv;
    float x1 = el[s1*NH + h] + erv;
    x0 = x0 > 0.f ? x0 : 0.2f * x0;          // leaky_relu(0.2)
    x1 = x1 > 0.f ? x1 : 0.2f * x1;

    // softmax over 16 edges within each head (lanes sharing h are stride-4)
    float m = fmaxf(x0, x1);
    m = fmaxf(m, __shfl_xor_sync(~0u, m, 4));
    m = fmaxf(m, __shfl_xor_sync(~0u, m, 8));
    m = fmaxf(m, __shfl_xor_sync(~0u, m, 16));
    float ex0 = __expf(x0 - m), ex1 = __expf(x1 - m);
    float sm = ex0 + ex1;
    sm += __shfl_xor_sync(~0u, sm, 4);
    sm += __shfl_xor_sync(~0u, sm, 8);
    sm += __shfl_xor_sync(~0u, sm, 16);
    float inv = __frcp_rn(sm);
    float a0 = ex0 * inv, a1 = ex1 * inv;
    int off0 = s0 * (NH*HID*2);              // byte offset of src row (512B)
    int off1 = s1 * (NH*HID*2);

    const char* base = reinterpret_cast<const char*>(f) + lane*16;
    const int hl = lane >> 3;                // head owning this lane's 16B slice
    float acc[8];
    #pragma unroll
    for (int q = 0; q < 8; q++) acc[q] = 0.f;

    #pragma unroll
    for (int j = 0; j < DEG; j++) {
        int srcl = ((j & 7) << 2) + hl;
        int   oj = __shfl_sync(~0u, (j < 8) ? off0 : off1, srcl);
        float aj = __shfl_sync(~0u, (j < 8) ? a0  : a1,  srcl);
        uint4 raw = *reinterpret_cast<const uint4*>(base + oj);
        float2 q0 = __half22float2(*reinterpret_cast<__half2*>(&raw.x));
        float2 q1 = __half22float2(*reinterpret_cast<__half2*>(&raw.y));
        float2 q2 = __half22float2(*reinterpret_cast<__half2*>(&raw.z));
        float2 q3 = __half22float2(*reinterpret_cast<__half2*>(&raw.w));
        acc[0] += aj*q0.x; acc[1] += aj*q0.y;
        acc[2] += aj*q1.x; acc[3] += aj*q1.y;
        acc[4] += aj*q2.x; acc[5] += aj*q2.y;
        acc[6] += aj*q3.x; acc[7] += aj*q3.y;
    }

    // bias + relu + store (lane owns dims [lane*8, lane*8+8) of the 256-wide row)
    int db = lane * 8;
    float4 b0 = *reinterpret_cast<const float4*>(bias + db);
    float4 b1 = *reinterpret_cast<const float4*>(bias + db + 4);
    float4 o0 = make_float4(fmaxf(acc[0]+b0.x, 0.f), fmaxf(acc[1]+b0.y, 0.f),
                            fmaxf(acc[2]+b0.z, 0.f), fmaxf(acc[3]+b0.w, 0.f));
    float4 o1 = make_float4(fmaxf(acc[4]+b1.x, 0.f), fmaxf(acc[5]+b1.y, 0.f),
                            fmaxf(acc[6]+b1.z, 0.f), fmaxf(acc[7]+b1.w, 0.f));
    float* dst = out + (long)v*(NH*HID) + db;
    *reinterpret_cast<float4*>(dst)     = o0;
    *reinterpret_cast<float4*>(dst + 4) = o1;
}

// ------------- layer-2 aggregation (1 head): warp per node -----------------
template<int NHh, bool RELU>
__global__ void agg_kernel(const __half* __restrict__ f, const float* __restrict__ el,
                           const float* __restrict__ er, const float* __restrict__ bias,
                           const int* __restrict__ src, float* __restrict__ out) {
    int gw   = (blockIdx.x * blockDim.x + threadIdx.x) >> 5;
    int lane = threadIdx.x & 31;
    if (gw >= NND * NHh) return;
    int v = gw / NHh, h = gw - v*NHh;

    float erv = er[v*NHh + h];
    int   off = 0;
    float e   = -1e30f;
    if (lane < DEG) {
        int s = src[v * DEG + lane];
        off = s * (NHh*HID*2);
        float x = el[s*NHh + h] + erv;
        e = x > 0.f ? x : 0.2f * x;
    }
    float m = e;
    #pragma unroll
    for (int o = 8; o > 0; o >>= 1) m = fmaxf(m, __shfl_xor_sync(~0u, m, o, 16));
    float ex = (lane < DEG) ? __expf(e - m) : 0.f;
    float sm = ex;
    #pragma unroll
    for (int o = 8; o > 0; o >>= 1) sm += __shfl_xor_sync(~0u, sm, o, 16);
    float alpha = ex / sm;

    int half_ = lane >> 4;
    int dl    = lane & 15;
    const char* base = reinterpret_cast<const char*>(f) + h*(HID*2) + dl*8;
    float4 acc = make_float4(0.f, 0.f, 0.f, 0.f);
    #pragma unroll
    for (int j = 0; j < DEG/2; j++) {
        int   eidx = 2*j + half_;
        int   oj = __shfl_sync(~0u, off,   eidx);
        float aj = __shfl_sync(~0u, alpha, eidx);
        uint2 raw = *reinterpret_cast<const uint2*>(base + oj);
        float2 f0 = __half22float2(*reinterpret_cast<__half2*>(&raw.x));
        float2 f1 = __half22float2(*reinterpret_cast<__half2*>(&raw.y));
        acc.x += aj * f0.x;
        acc.y += aj * f0.y;
        acc.z += aj * f1.x;
        acc.w += aj * f1.y;
    }
    acc.x += __shfl_xor_sync(~0u, acc.x, 16);
    acc.y += __shfl_xor_sync(~0u, acc.y, 16);
    acc.z += __shfl_xor_sync(~0u, acc.z, 16);
    acc.w += __shfl_xor_sync(~0u, acc.w, 16);
    if (half_ == 0) {
        int d = dl * 4;
        float4 b4 = *reinterpret_cast<const float4*>(&bias[h*HID + d]);
        float4 o4 = make_float4(acc.x + b4.x, acc.y + b4.y, acc.z + b4.z, acc.w + b4.w);
        if (RELU) {
            o4.x = fmaxf(o4.x, 0.f); o4.y = fmaxf(o4.y, 0.f);
            o4.z = fmaxf(o4.z, 0.f); o4.w = fmaxf(o4.w, 0.f);
        }
        *reinterpret_cast<float4*>(&out[((long)v * NHh + h) * HID + d]) = o4;
    }
}

// ---------------- scores, labels, per-row loss ----------------
__global__ void score_kernel(const float* __restrict__ h2, const int* __restrict__ uid,
                             const int* __restrict__ iid, float* __restrict__ out) {
    int i = blockIdx.x;
    int d = threadIdx.x;
    float su = h2[(long)uid[i] * HID + d];
    float si = h2[(long)iid[i] * HID + d];
    float sc = su * si;
    out[1 + i*BATCH + d] = sc;
    out[1 + BATCH*BATCH + i*BATCH + d] = (i == d) ? 1.f : 0.f;

    __shared__ float buf[BATCH];
    __shared__ float diag;
    if (d == i) diag = sc;
    buf[d] = sc;
    __syncthreads();
    for (int st = 32; st > 0; st >>= 1) {
        if (d < st) buf[d] = fmaxf(buf[d], buf[d + st]);
        __syncthreads();
    }
    float mx = buf[0];
    __syncthreads();
    buf[d] = expf(sc - mx);
    __syncthreads();
    for (int st = 32; st > 0; st >>= 1) {
        if (d < st) buf[d] += buf[d + st];
        __syncthreads();
    }
    if (d == 0) {
        float lse = mx + logf(buf[0]);
        g_loss[i] = lse - diag;
    }
}

__global__ void finalize_kernel(float* __restrict__ out) {
    if (threadIdx.x == 0) {
        float s = 0.f;
        for (int i = 0; i < BATCH; i++) s += g_loss[i];
        out[0] = s / (float)BATCH;
    }
}

// ---------------- launcher ----------------
extern "C" void kernel_launch(void* const* d_in, const int* in_sizes, int n_in,
                              void* d_out, int out_size) {
    const int*   feat_ids = (const int*)  d_in[0];
    const int*   src      = (const int*)  d_in[1];
    const int*   user_ids = (const int*)  d_in[3];
    const int*   item_ids = (const int*)  d_in[4];
    const float* emb      = (const float*)d_in[5];
    const float* W1       = (const float*)d_in[6];
    const float* a_l1     = (const float*)d_in[7];
    const float* a_r1     = (const float*)d_in[8];
    const float* b1       = (const float*)d_in[9];
    const float* W2       = (const float*)d_in[10];
    const float* a_l2     = (const float*)d_in[11];
    const float* a_r2     = (const float*)d_in[12];
    const float* b2       = (const float*)d_in[13];
    float* out = (float*)d_out;

    __half *f1h, *f2h;
    float *el1, *er1, *h1, *el2, *er2, *h2;
    cudaGetSymbolAddress((void**)&f1h, g_f1h);
    cudaGetSymbolAddress((void**)&el1, g_el1);
    cudaGetSymbolAddress((void**)&er1, g_er1);
    cudaGetSymbolAddress((void**)&h1,  g_h1);
    cudaGetSymbolAddress((void**)&f2h, g_f2h);
    cudaGetSymbolAddress((void**)&el2, g_el2);
    cudaGetSymbolAddress((void**)&er2, g_er2);
    cudaGetSymbolAddress((void**)&h2,  g_h2);

    // layer 1: f1 = emb[feat_ids] @ W1 (50000x128x256) + fused el1/er1, fp16 out
    gemm_fused<64,256,16,4><<<(NND+63)/64, 256>>>(
        emb, feat_ids, W1, a_l1, a_r1, f1h, el1, er1, NND, IN_F);
    agg4_kernel<<<(NND*32 + 255)/256, 256>>>(f1h, el1, er1, b1, src, h1);

    // layer 2: f2 = h1 @ W2 (50000x256x64) + fused el2/er2, fp16 out
    gemm_fused<128,64,32,1><<<(NND+127)/128, 128>>>(
        h1, nullptr, W2, a_l2, a_r2, f2h, el2, er2, NND, NH*HID);
    agg_kernel<1,false><<<NND/8, 256>>>(f2h, el2, er2, b2, src, h2);

    score_kernel<<<BATCH, BATCH>>>(h2, user_ids, item_ids, out);
    finalize_kernel<<<1, 32>>>(out);
}

// round 9
// speedup vs baseline: 2.4892x; 1.9554x over previous
#include <cuda_runtime.h>
#include <cuda_fp16.h>

// ---------------- problem constants ----------------
#define NND   50000
#define DEG   16
#define IN_F  128
#define HID   64
#define NH    4
#define BATCH 64

// compacted sizes
#define NT1   128                 // targets = [uid(64), iid(64)]
#define NS1   (NT1*DEG + NT1)     // 2176 rows where h1/f2 needed
#define NE1   (NS1*DEG)           // 34816 layer-1 edge slots
#define NS0   (NE1 + NS1)         // 36992 rows where f1/el1/er1 needed

typedef unsigned long long ull;

// ---------------- scratch ----------------
__device__ int    g_S1[NS1];            // global node id per local layer-1 row
__device__ int    g_gidx0[NS0];         // emb row (feat_ids[...]) per local f1 row
__device__ __half g_f1loc[NS0*NH*HID];  // 36992 x 256 fp16
__device__ float  g_el1loc[NS0*NH];
__device__ float  g_er1loc[NS0*NH];
__device__ float  g_h1loc[NS1*NH*HID];  // 2176 x 256 fp32
__device__ __half g_f2loc[NS1*HID];     // 2176 x 64 fp16
__device__ float  g_el2loc[NS1];
__device__ float  g_er2loc[NS1];
__device__ float  g_h2loc[NT1*HID];     // 128 x 64
__device__ float  g_loss[BATCH];

// ---------------- packed f32x2 helpers ----------------
__device__ __forceinline__ ull pack_dup(float x) {
    ull r; asm("mov.b64 %0, {%1, %1};" : "=l"(r) : "f"(x)); return r;
}
__device__ __forceinline__ void ffma2(ull& acc, ull a, ull b) {
    asm("fma.rn.f32x2 %0, %1, %2, %0;" : "+l"(acc) : "l"(a), "l"(b));
}
__device__ __forceinline__ float2 unpack2(ull v) {
    float2 f; asm("mov.b64 {%0, %1}, %2;" : "=f"(f.x), "=f"(f.y) : "l"(v)); return f;
}

// ---------------- index building ----------------
__device__ __forceinline__ int target_of(int x, const int* uid, const int* iid) {
    return (x < BATCH) ? uid[x] : iid[x - BATCH];
}
__global__ void build_s1(const int* __restrict__ src, const int* __restrict__ uid,
                         const int* __restrict__ iid) {
    int i = blockIdx.x*blockDim.x + threadIdx.x;
    if (i >= NS1) return;
    if (i < NT1*DEG) {
        int t = target_of(i >> 4, uid, iid);
        g_S1[i] = src[t*DEG + (i & 15)];
    } else {
        g_S1[i] = target_of(i - NT1*DEG, uid, iid);
    }
}
__global__ void build_gidx(const int* __restrict__ src, const int* __restrict__ feat_ids) {
    int p = blockIdx.x*blockDim.x + threadIdx.x;
    if (p >= NS0) return;
    int s;
    if (p < NE1) {
        int u = g_S1[p >> 4];
        s = src[u*DEG + (p & 15)];
    } else {
        s = g_S1[p - NE1];
    }
    g_gidx0[p] = feat_ids[s];
}

// ---------------- GEMM with 2-D warp tiling + fused attention dots ----------
template<int BM,int BN,int BK,int NHh>
__global__ __launch_bounds__((BM/8)*(BN/8))
void gemm_fused(const float* __restrict__ A, const int* __restrict__ gidx,
                const float* __restrict__ B,
                const float* __restrict__ al, const float* __restrict__ ar,
                __half* __restrict__ Ch, float* __restrict__ el, float* __restrict__ er,
                int M, int K) {
    constexpr int TM = 8, TN = 8;
    constexpr int NT = (BM/TM)*(BN/TN);
    constexpr int NWARP = NT/32;
    constexpr int WN = BN/64;
    constexpr int WM = NWARP/WN;
    static_assert(WM*32 == BM && WN*64 == BN, "warp tiling");
    __shared__ float As[BK][BM];
    __shared__ float Bs[BK][BN];
    const int tid  = threadIdx.x;
    const int warp = tid >> 5;
    const int lane = tid & 31;
    const int wm = warp % WM, wn = warp / WM;
    const int lr = lane >> 3, lc = lane & 7;
    const int ty = wm*4 + lr;
    const int tx = wn*8 + lc;
    const int m0 = blockIdx.x * BM;

    constexpr int A_F4 = BM*BK/4;
    constexpr int A_IT = A_F4 / NT;
    static_assert(A_IT >= 1 && A_F4 % NT == 0, "A tiling");
    long arow[A_IT];
    #pragma unroll
    for (int r = 0; r < A_IT; r++) {
        int idx = tid + r*NT;
        int mA  = idx / (BK/4);
        int gm  = m0 + mA;
        int row = (gm < M) ? (gidx ? gidx[gm] : gm) : 0;
        arow[r] = (long)row * K;
    }
    constexpr int B_F4 = BK*BN/4;
    constexpr int B_IT = B_F4 / NT;
    static_assert(B_IT >= 1 && B_F4 % NT == 0, "B tiling");

    ull acc2[TM/2][TN];
    #pragma unroll
    for (int i = 0; i < TM/2; i++)
        #pragma unroll
        for (int j = 0; j < TN; j++) acc2[i][j] = 0ull;

    for (int k0 = 0; k0 < K; k0 += BK) {
        #pragma unroll
        for (int r = 0; r < A_IT; r++) {
            int idx = tid + r*NT;
            int mA  = idx / (BK/4);
            int kq  = idx % (BK/4);
            float4 v = *reinterpret_cast<const float4*>(A + arow[r] + k0 + kq*4);
            As[kq*4+0][mA] = v.x;
            As[kq*4+1][mA] = v.y;
            As[kq*4+2][mA] = v.z;
            As[kq*4+3][mA] = v.w;
        }
        #pragma unroll
        for (int r = 0; r < B_IT; r++) {
            int idx = tid + r*NT;
            int kB  = idx / (BN/4);
            int nq  = idx % (BN/4);
            float4 v = *reinterpret_cast<const float4*>(B + (long)(k0+kB)*BN + nq*4);
            *reinterpret_cast<float4*>(&Bs[kB][nq*4]) = v;
        }
        __syncthreads();
        #pragma unroll
        for (int k = 0; k < BK; k++) {
            ull a2[TM/2];
            const ull* ap = reinterpret_cast<const ull*>(&As[k][ty*TM]);
            #pragma unroll
            for (int i = 0; i < TM/2; i++) a2[i] = ap[i];
            float4 blo = *reinterpret_cast<const float4*>(&Bs[k][tx*TN]);
            float4 bhi = *reinterpret_cast<const float4*>(&Bs[k][tx*TN+4]);
            ull b2[TN];
            b2[0]=pack_dup(blo.x); b2[1]=pack_dup(blo.y);
            b2[2]=pack_dup(blo.z); b2[3]=pack_dup(blo.w);
            b2[4]=pack_dup(bhi.x); b2[5]=pack_dup(bhi.y);
            b2[6]=pack_dup(bhi.z); b2[7]=pack_dup(bhi.w);
            #pragma unroll
            for (int i = 0; i < TM/2; i++)
                #pragma unroll
                for (int j = 0; j < TN; j++) ffma2(acc2[i][j], a2[i], b2[j]);
        }
        __syncthreads();
    }

    float acc[TM][TN];
    #pragma unroll
    for (int i = 0; i < TM/2; i++)
        #pragma unroll
        for (int j = 0; j < TN; j++) {
            float2 p = unpack2(acc2[i][j]);
            acc[2*i  ][j] = p.x;
            acc[2*i+1][j] = p.y;
        }

    float alr[TN], arr[TN];
    #pragma unroll
    for (int j = 0; j < TN; j++) { int n = tx*TN + j; alr[j] = al[n]; arr[j] = ar[n]; }

    #pragma unroll
    for (int i = 0; i < TM; i++) {
        int gm = m0 + ty*TM + i;
        float sl = 0.f, sr = 0.f;
        #pragma unroll
        for (int j = 0; j < TN; j++) { sl += acc[i][j]*alr[j]; sr += acc[i][j]*arr[j]; }
        #pragma unroll
        for (int o = 1; o < 8; o <<= 1) {
            sl += __shfl_xor_sync(~0u, sl, o);
            sr += __shfl_xor_sync(~0u, sr, o);
        }
        if (gm < M) {
            __half2 p0 = __floats2half2_rn(acc[i][0], acc[i][1]);
            __half2 p1 = __floats2half2_rn(acc[i][2], acc[i][3]);
            __half2 p2 = __floats2half2_rn(acc[i][4], acc[i][5]);
            __half2 p3 = __floats2half2_rn(acc[i][6], acc[i][7]);
            uint4 w;
            w.x = *reinterpret_cast<unsigned*>(&p0);
            w.y = *reinterpret_cast<unsigned*>(&p1);
            w.z = *reinterpret_cast<unsigned*>(&p2);
            w.w = *reinterpret_cast<unsigned*>(&p3);
            *reinterpret_cast<uint4*>(&Ch[(long)gm*BN + tx*TN]) = w;
            if (lc == 0) {
                el[(long)gm*NHh + wn] = sl;
                er[(long)gm*NHh + wn] = sr;
            }
        }
    }
}

// -------- compact layer-1 aggregation: one warp per local node (4 heads) -----
// Edge rows are CONTIGUOUS: node i's edges live at f1loc rows [16i, 16i+16).
__global__ void agg1c_kernel(const __half* __restrict__ f, const float* __restrict__ el,
                             const float* __restrict__ er, const float* __restrict__ bias,
                             float* __restrict__ out) {
    int v    = (blockIdx.x * blockDim.x + threadIdx.x) >> 5;
    int lane = threadIdx.x & 31;
    if (v >= NS1) return;
    const int h    = lane & 3;
    const int eidx = lane >> 2;              // edge 0..7 (+8 for second)

    float erv = er[(NE1 + v)*NH + h];
    int p0 = v*DEG + eidx, p1 = p0 + 8;
    float x0 = el[p0*NH + h] + erv;
    float x1 = el[p1*NH + h] + erv;
    x0 = x0 > 0.f ? x0 : 0.2f * x0;
    x1 = x1 > 0.f ? x1 : 0.2f * x1;

    float m = fmaxf(x0, x1);
    m = fmaxf(m, __shfl_xor_sync(~0u, m, 4));
    m = fmaxf(m, __shfl_xor_sync(~0u, m, 8));
    m = fmaxf(m, __shfl_xor_sync(~0u, m, 16));
    float ex0 = __expf(x0 - m), ex1 = __expf(x1 - m);
    float sm = ex0 + ex1;
    sm += __shfl_xor_sync(~0u, sm, 4);
    sm += __shfl_xor_sync(~0u, sm, 8);
    sm += __shfl_xor_sync(~0u, sm, 16);
    float inv = __frcp_rn(sm);
    float a0 = ex0 * inv, a1 = ex1 * inv;

    const char* base = reinterpret_cast<const char*>(f) + (long)v*DEG*(NH*HID*2) + lane*16;
    const int hl = lane >> 3;                // head owning this lane's 16B slice
    float acc[8];
    #pragma unroll
    for (int q = 0; q < 8; q++) acc[q] = 0.f;

    #pragma unroll
    for (int j = 0; j < DEG; j++) {
        int srcl = ((j & 7) << 2) + hl;
        float aj = __shfl_sync(~0u, (j < 8) ? a0 : a1, srcl);
        uint4 raw = *reinterpret_cast<const uint4*>(base + (long)j*(NH*HID*2));
        float2 q0 = __half22float2(*reinterpret_cast<__half2*>(&raw.x));
        float2 q1 = __half22float2(*reinterpret_cast<__half2*>(&raw.y));
        float2 q2 = __half22float2(*reinterpret_cast<__half2*>(&raw.z));
        float2 q3 = __half22float2(*reinterpret_cast<__half2*>(&raw.w));
        acc[0] += aj*q0.x; acc[1] += aj*q0.y;
        acc[2] += aj*q1.x; acc[3] += aj*q1.y;
        acc[4] += aj*q2.x; acc[5] += aj*q2.y;
        acc[6] += aj*q3.x; acc[7] += aj*q3.y;
    }

    int db = lane * 8;
    float4 b0 = *reinterpret_cast<const float4*>(bias + db);
    float4 b1 = *reinterpret_cast<const float4*>(bias + db + 4);
    float4 o0 = make_float4(fmaxf(acc[0]+b0.x, 0.f), fmaxf(acc[1]+b0.y, 0.f),
                            fmaxf(acc[2]+b0.z, 0.f), fmaxf(acc[3]+b0.w, 0.f));
    float4 o1 = make_float4(fmaxf(acc[4]+b1.x, 0.f), fmaxf(acc[5]+b1.y, 0.f),
                            fmaxf(acc[6]+b1.z, 0.f), fmaxf(acc[7]+b1.w, 0.f));
    float* dst = out + (long)v*(NH*HID) + db;
    *reinterpret_cast<float4*>(dst)     = o0;
    *reinterpret_cast<float4*>(dst + 4) = o1;
}

// -------- compact layer-2 aggregation: one warp per target (1 head) ---------
__global__ void agg2c_kernel(const __half* __restrict__ f, const float* __restrict__ el,
                             const float* __restrict__ er, const float* __restrict__ bias,
                             float* __restrict__ out) {
    int i    = (blockIdx.x * blockDim.x + threadIdx.x) >> 5;
    int lane = threadIdx.x & 31;
    if (i >= NT1) return;

    float erv = er[NT1*DEG + i];
    float e = -1e30f;
    if (lane < DEG) {
        float x = el[i*DEG + lane] + erv;
        e = x > 0.f ? x : 0.2f * x;
    }
    float m = e;
    #pragma unroll
    for (int o = 8; o > 0; o >>= 1) m = fmaxf(m, __shfl_xor_sync(~0u, m, o, 16));
    float ex = (lane < DEG) ? __expf(e - m) : 0.f;
    float sm = ex;
    #pragma unroll
    for (int o = 8; o > 0; o >>= 1) sm += __shfl_xor_sync(~0u, sm, o, 16);
    float alpha = ex / sm;

    int half_ = lane >> 4;
    int dl    = lane & 15;
    const char* base = reinterpret_cast<const char*>(f) + (long)i*DEG*(HID*2) + dl*8;
    float4 acc = make_float4(0.f, 0.f, 0.f, 0.f);
    #pragma unroll
    for (int j = 0; j < DEG/2; j++) {
        int   eidx = 2*j + half_;
        float aj = __shfl_sync(~0u, alpha, eidx);
        uint2 raw = *reinterpret_cast<const uint2*>(base + eidx*(HID*2));
        float2 f0 = __half22float2(*reinterpret_cast<__half2*>(&raw.x));
        float2 f1 = __half22float2(*reinterpret_cast<__half2*>(&raw.y));
        acc.x += aj * f0.x;
        acc.y += aj * f0.y;
        acc.z += aj * f1.x;
        acc.w += aj * f1.y;
    }
    acc.x += __shfl_xor_sync(~0u, acc.x, 16);
    acc.y += __shfl_xor_sync(~0u, acc.y, 16);
    acc.z += __shfl_xor_sync(~0u, acc.z, 16);
    acc.w += __shfl_xor_sync(~0u, acc.w, 16);
    if (half_ == 0) {
        int d = dl * 4;
        float4 b4 = *reinterpret_cast<const float4*>(&bias[d]);
        float4 o4 = make_float4(acc.x + b4.x, acc.y + b4.y, acc.z + b4.z, acc.w + b4.w);
        *reinterpret_cast<float4*>(&out[(long)i*HID + d]) = o4;
    }
}

// ---------------- scores, labels, per-row loss (local h2) ----------------
__global__ void score_kernel(const float* __restrict__ h2loc, float* __restrict__ out) {
    int i = blockIdx.x;     // 0..63
    int d = threadIdx.x;    // 0..63
    float su = h2loc[(long)i * HID + d];
    float si = h2loc[(long)(BATCH + i) * HID + d];
    float sc = su * si;
    out[1 + i*BATCH + d] = sc;
    out[1 + BATCH*BATCH + i*BATCH + d] = (i == d) ? 1.f : 0.f;

    __shared__ float buf[BATCH];
    __shared__ float diag;
    if (d == i) diag = sc;
    buf[d] = sc;
    __syncthreads();
    for (int st = 32; st > 0; st >>= 1) {
        if (d < st) buf[d] = fmaxf(buf[d], buf[d + st]);
        __syncthreads();
    }
    float mx = buf[0];
    __syncthreads();
    buf[d] = expf(sc - mx);
    __syncthreads();
    for (int st = 32; st > 0; st >>= 1) {
        if (d < st) buf[d] += buf[d + st];
        __syncthreads();
    }
    if (d == 0) {
        float lse = mx + logf(buf[0]);
        g_loss[i] = lse - diag;
    }
}

__global__ void finalize_kernel(float* __restrict__ out) {
    if (threadIdx.x == 0) {
        float s = 0.f;
        for (int i = 0; i < BATCH; i++) s += g_loss[i];
        out[0] = s / (float)BATCH;
    }
}

// ---------------- launcher ----------------
extern "C" void kernel_launch(void* const* d_in, const int* in_sizes, int n_in,
                              void* d_out, int out_size) {
    const int*   feat_ids = (const int*)  d_in[0];
    const int*   src      = (const int*)  d_in[1];
    const int*   user_ids = (const int*)  d_in[3];
    const int*   item_ids = (const int*)  d_in[4];
    const float* emb      = (const float*)d_in[5];
    const float* W1       = (const float*)d_in[6];
    const float* a_l1     = (const float*)d_in[7];
    const float* a_r1     = (const float*)d_in[8];
    const float* b1       = (const float*)d_in[9];
    const float* W2       = (const float*)d_in[10];
    const float* a_l2     = (const float*)d_in[11];
    const float* a_r2     = (const float*)d_in[12];
    const float* b2       = (const float*)d_in[13];
    float* out = (float*)d_out;

    int *gidx0;
    __half *f1loc, *f2loc;
    float *el1, *er1, *h1loc, *el2, *er2, *h2loc;
    cudaGetSymbolAddress((void**)&gidx0, g_gidx0);
    cudaGetSymbolAddress((void**)&f1loc, g_f1loc);
    cudaGetSymbolAddress((void**)&el1,   g_el1loc);
    cudaGetSymbolAddress((void**)&er1,   g_er1loc);
    cudaGetSymbolAddress((void**)&h1loc, g_h1loc);
    cudaGetSymbolAddress((void**)&f2loc, g_f2loc);
    cudaGetSymbolAddress((void**)&el2,   g_el2loc);
    cudaGetSymbolAddress((void**)&er2,   g_er2loc);
    cudaGetSymbolAddress((void**)&h2loc, g_h2loc);

    // index construction (tiny)
    build_s1<<<(NS1 + 255)/256, 256>>>(src, user_ids, item_ids);
    build_gidx<<<(NS0 + 255)/256, 256>>>(src, feat_ids);

    // layer 1 GEMM over 36,992 gathered emb rows (exactly 578 x 64)
    gemm_fused<64,256,16,4><<<NS0/64, 256>>>(
        emb, gidx0, W1, a_l1, a_r1, f1loc, el1, er1, NS0, IN_F);
    // compact agg1: 2,176 nodes, contiguous edge rows
    agg1c_kernel<<<(NS1*32 + 255)/256, 256>>>(f1loc, el1, er1, b1, h1loc);

    // layer 2 GEMM over 2,176 local rows (exactly 17 x 128)
    gemm_fused<128,64,32,1><<<NS1/128, 128>>>(
        h1loc, nullptr, W2, a_l2, a_r2, f2loc, el2, er2, NS1, NH*HID);
    // compact agg2: 128 target nodes
    agg2c_kernel<<<(NT1*32)/256, 256>>>(f2loc, el2, er2, b2, h2loc);

    score_kernel<<<BATCH, BATCH>>>(h2loc, out);
    finalize_kernel<<<1, 32>>>(out);
}

// round 10
// speedup vs baseline: 2.6053x; 1.0467x over previous
#include <cuda_runtime.h>
#include <cuda_fp16.h>

// ---------------- problem constants ----------------
#define NND   50000
#define DEG   16
#define IN_F  128
#define HID   64
#define NH    4
#define BATCH 64

// compacted sizes
#define NT1   128                 // targets = [uid(64), iid(64)]
#define NS1   (NT1*DEG + NT1)     // 2176 rows where h1/f2 needed
#define NE1   (NS1*DEG)           // 34816 layer-1 edge slots
#define NS0   (NE1 + NS1)         // 36992 layer-0 row slots (before dedup)

typedef unsigned long long ull;

// ---------------- scratch ----------------
__device__ int    g_S1[NS1];            // global node id per local layer-1 row
__device__ int    g_mark[NND];          // feat-id -> slot+1 (0 = unused)
__device__ int    g_fid[NS0];           // feat id per layer-0 slot
__device__ int    g_lrow[NS0];          // layer-0 slot -> unique f1 row
__device__ int    g_ulist[NS0];         // unique feat ids (GEMM1 gather index)
__device__ int    g_ucount;
__device__ __half g_f1loc[NS0*NH*HID];  // unique rows x 256 fp16
__device__ float  g_el1loc[NS0*NH];
__device__ float  g_er1loc[NS0*NH];
__device__ float  g_h1loc[NS1*NH*HID];  // 2176 x 256 fp32
__device__ __half g_f2loc[NS1*HID];     // 2176 x 64 fp16
__device__ float  g_el2loc[NS1];
__device__ float  g_er2loc[NS1];
__device__ float  g_h2loc[NT1*HID];     // 128 x 64
__device__ float  g_loss[BATCH];

// ---------------- packed f32x2 helpers ----------------
__device__ __forceinline__ ull pack_dup(float x) {
    ull r; asm("mov.b64 %0, {%1, %1};" : "=l"(r) : "f"(x)); return r;
}
__device__ __forceinline__ void ffma2(ull& acc, ull a, ull b) {
    asm("fma.rn.f32x2 %0, %1, %2, %0;" : "+l"(acc) : "l"(a), "l"(b));
}
__device__ __forceinline__ float2 unpack2(ull v) {
    float2 f; asm("mov.b64 {%0, %1}, %2;" : "=f"(f.x), "=f"(f.y) : "l"(v)); return f;
}

// ---------------- index building ----------------
__global__ void clear_marks() {
    int i = blockIdx.x*blockDim.x + threadIdx.x;
    if (i < NND) g_mark[i] = 0;
    if (i == 0) g_ucount = 0;
}
__device__ __forceinline__ int target_of(int x, const int* uid, const int* iid) {
    return (x < BATCH) ? uid[x] : iid[x - BATCH];
}
__global__ void build_s1(const int* __restrict__ src, const int* __restrict__ uid,
                         const int* __restrict__ iid) {
    int i = blockIdx.x*blockDim.x + threadIdx.x;
    if (i >= NS1) return;
    if (i < NT1*DEG) {
        int t = target_of(i >> 4, uid, iid);
        g_S1[i] = src[t*DEG + (i & 15)];
    } else {
        g_S1[i] = target_of(i - NT1*DEG, uid, iid);
    }
}
__global__ void mark_kernel(const int* __restrict__ src, const int* __restrict__ feat_ids) {
    int p = blockIdx.x*blockDim.x + threadIdx.x;
    if (p >= NS0) return;
    int s;
    if (p < NE1) {
        int u = g_S1[p >> 4];
        s = src[u*DEG + (p & 15)];
    } else {
        s = g_S1[p - NE1];
    }
    int fid = feat_ids[s];
    g_fid[p] = fid;
    g_mark[fid] = 1;
}
__global__ void compact_kernel() {
    int v = blockIdx.x*blockDim.x + threadIdx.x;
    if (v >= NND) return;
    if (g_mark[v]) {
        int slot = atomicAdd(&g_ucount, 1);
        g_ulist[slot] = v;
        g_mark[v] = slot + 1;
    }
}
__global__ void lrow_kernel() {
    int p = blockIdx.x*blockDim.x + threadIdx.x;
    if (p >= NS0) return;
    g_lrow[p] = g_mark[g_fid[p]] - 1;
}

// ---------------- GEMM with 2-D warp tiling + fused attention dots ----------
// Mdyn != nullptr -> row count read from device (dedup'd count)
template<int BM,int BN,int BK,int NHh>
__global__ __launch_bounds__((BM/8)*(BN/8))
void gemm_fused(const float* __restrict__ A, const int* __restrict__ gidx,
                const float* __restrict__ B,
                const float* __restrict__ al, const float* __restrict__ ar,
                __half* __restrict__ Ch, float* __restrict__ el, float* __restrict__ er,
                int M, const int* __restrict__ Mdyn, int K) {
    if (Mdyn) M = *Mdyn;
    const int m0 = blockIdx.x * BM;
    if (m0 >= M) return;

    constexpr int TM = 8, TN = 8;
    constexpr int NT = (BM/TM)*(BN/TN);
    constexpr int NWARP = NT/32;
    constexpr int WN = BN/64;
    constexpr int WM = NWARP/WN;
    static_assert(WM*32 == BM && WN*64 == BN, "warp tiling");
    __shared__ float As[BK][BM];
    __shared__ float Bs[BK][BN];
    const int tid  = threadIdx.x;
    const int warp = tid >> 5;
    const int lane = tid & 31;
    const int wm = warp % WM, wn = warp / WM;
    const int lr = lane >> 3, lc = lane & 7;
    const int ty = wm*4 + lr;
    const int tx = wn*8 + lc;

    constexpr int A_F4 = BM*BK/4;
    constexpr int A_IT = A_F4 / NT;
    static_assert(A_IT >= 1 && A_F4 % NT == 0, "A tiling");
    long arow[A_IT];
    #pragma unroll
    for (int r = 0; r < A_IT; r++) {
        int idx = tid + r*NT;
        int mA  = idx / (BK/4);
        int gm  = m0 + mA;
        int row = (gm < M) ? (gidx ? gidx[gm] : gm) : (gidx ? gidx[0] : 0);
        arow[r] = (long)row * K;
    }
    constexpr int B_F4 = BK*BN/4;
    constexpr int B_IT = B_F4 / NT;
    static_assert(B_IT >= 1 && B_F4 % NT == 0, "B tiling");

    ull acc2[TM/2][TN];
    #pragma unroll
    for (int i = 0; i < TM/2; i++)
        #pragma unroll
        for (int j = 0; j < TN; j++) acc2[i][j] = 0ull;

    for (int k0 = 0; k0 < K; k0 += BK) {
        #pragma unroll
        for (int r = 0; r < A_IT; r++) {
            int idx = tid + r*NT;
            int mA  = idx / (BK/4);
            int kq  = idx % (BK/4);
            float4 v = *reinterpret_cast<const float4*>(A + arow[r] + k0 + kq*4);
            As[kq*4+0][mA] = v.x;
            As[kq*4+1][mA] = v.y;
            As[kq*4+2][mA] = v.z;
            As[kq*4+3][mA] = v.w;
        }
        #pragma unroll
        for (int r = 0; r < B_IT; r++) {
            int idx = tid + r*NT;
            int kB  = idx / (BN/4);
            int nq  = idx % (BN/4);
            float4 v = *reinterpret_cast<const float4*>(B + (long)(k0+kB)*BN + nq*4);
            *reinterpret_cast<float4*>(&Bs[kB][nq*4]) = v;
        }
        __syncthreads();
        #pragma unroll
        for (int k = 0; k < BK; k++) {
            ull a2[TM/2];
            const ull* ap = reinterpret_cast<const ull*>(&As[k][ty*TM]);
            #pragma unroll
            for (int i = 0; i < TM/2; i++) a2[i] = ap[i];
            float4 blo = *reinterpret_cast<const float4*>(&Bs[k][tx*TN]);
            float4 bhi = *reinterpret_cast<const float4*>(&Bs[k][tx*TN+4]);
            ull b2[TN];
            b2[0]=pack_dup(blo.x); b2[1]=pack_dup(blo.y);
            b2[2]=pack_dup(blo.z); b2[3]=pack_dup(blo.w);
            b2[4]=pack_dup(bhi.x); b2[5]=pack_dup(bhi.y);
            b2[6]=pack_dup(bhi.z); b2[7]=pack_dup(bhi.w);
            #pragma unroll
            for (int i = 0; i < TM/2; i++)
                #pragma unroll
                for (int j = 0; j < TN; j++) ffma2(acc2[i][j], a2[i], b2[j]);
        }
        __syncthreads();
    }

    float acc[TM][TN];
    #pragma unroll
    for (int i = 0; i < TM/2; i++)
        #pragma unroll
        for (int j = 0; j < TN; j++) {
            float2 p = unpack2(acc2[i][j]);
            acc[2*i  ][j] = p.x;
            acc[2*i+1][j] = p.y;
        }

    float alr[TN], arr[TN];
    #pragma unroll
    for (int j = 0; j < TN; j++) { int n = tx*TN + j; alr[j] = al[n]; arr[j] = ar[n]; }

    #pragma unroll
    for (int i = 0; i < TM; i++) {
        int gm = m0 + ty*TM + i;
        float sl = 0.f, sr = 0.f;
        #pragma unroll
        for (int j = 0; j < TN; j++) { sl += acc[i][j]*alr[j]; sr += acc[i][j]*arr[j]; }
        #pragma unroll
        for (int o = 1; o < 8; o <<= 1) {
            sl += __shfl_xor_sync(~0u, sl, o);
            sr += __shfl_xor_sync(~0u, sr, o);
        }
        if (gm < M) {
            __half2 p0 = __floats2half2_rn(acc[i][0], acc[i][1]);
            __half2 p1 = __floats2half2_rn(acc[i][2], acc[i][3]);
            __half2 p2 = __floats2half2_rn(acc[i][4], acc[i][5]);
            __half2 p3 = __floats2half2_rn(acc[i][6], acc[i][7]);
            uint4 w;
            w.x = *reinterpret_cast<unsigned*>(&p0);
            w.y = *reinterpret_cast<unsigned*>(&p1);
            w.z = *reinterpret_cast<unsigned*>(&p2);
            w.w = *reinterpret_cast<unsigned*>(&p3);
            *reinterpret_cast<uint4*>(&Ch[(long)gm*BN + tx*TN]) = w;
            if (lc == 0) {
                el[(long)gm*NHh + wn] = sl;
                er[(long)gm*NHh + wn] = sr;
            }
        }
    }
}

// -------- layer-1 aggregation: one warp per local node (4 heads), lrow gather --
__global__ void agg1c_kernel(const __half* __restrict__ f, const float* __restrict__ el,
                             const float* __restrict__ er, const float* __restrict__ bias,
                             float* __restrict__ out) {
    int v    = (blockIdx.x * blockDim.x + threadIdx.x) >> 5;
    int lane = threadIdx.x & 31;
    if (v >= NS1) return;
    const int h    = lane & 3;
    const int eidx = lane >> 2;              // edge 0..7 (+8 for second)

    int ru = g_lrow[NE1 + v];                // unique row of node v itself
    float erv = er[ru*NH + h];
    int r0 = g_lrow[v*DEG + eidx];
    int r1 = g_lrow[v*DEG + eidx + 8];
    float x0 = el[r0*NH + h] + erv;
    float x1 = el[r1*NH + h] + erv;
    x0 = x0 > 0.f ? x0 : 0.2f * x0;
    x1 = x1 > 0.f ? x1 : 0.2f * x1;

    float m = fmaxf(x0, x1);
    m = fmaxf(m, __shfl_xor_sync(~0u, m, 4));
    m = fmaxf(m, __shfl_xor_sync(~0u, m, 8));
    m = fmaxf(m, __shfl_xor_sync(~0u, m, 16));
    float ex0 = __expf(x0 - m), ex1 = __expf(x1 - m);
    float sm = ex0 + ex1;
    sm += __shfl_xor_sync(~0u, sm, 4);
    sm += __shfl_xor_sync(~0u, sm, 8);
    sm += __shfl_xor_sync(~0u, sm, 16);
    float inv = __frcp_rn(sm);
    float a0 = ex0 * inv, a1 = ex1 * inv;
    int off0 = r0 * (NH*HID*2);              // byte offset of unique row (512B)
    int off1 = r1 * (NH*HID*2);

    const char* base = reinterpret_cast<const char*>(f) + lane*16;
    const int hl = lane >> 3;
    float acc[8];
    #pragma unroll
    for (int q = 0; q < 8; q++) acc[q] = 0.f;

    #pragma unroll
    for (int j = 0; j < DEG; j++) {
        int srcl = ((j & 7) << 2) + hl;
        int   oj = __shfl_sync(~0u, (j < 8) ? off0 : off1, srcl);
        float aj = __shfl_sync(~0u, (j < 8) ? a0  : a1,  srcl);
        uint4 raw = *reinterpret_cast<const uint4*>(base + oj);
        float2 q0 = __half22float2(*reinterpret_cast<__half2*>(&raw.x));
        float2 q1 = __half22float2(*reinterpret_cast<__half2*>(&raw.y));
        float2 q2 = __half22float2(*reinterpret_cast<__half2*>(&raw.z));
        float2 q3 = __half22float2(*reinterpret_cast<__half2*>(&raw.w));
        acc[0] += aj*q0.x; acc[1] += aj*q0.y;
        acc[2] += aj*q1.x; acc[3] += aj*q1.y;
        acc[4] += aj*q2.x; acc[5] += aj*q2.y;
        acc[6] += aj*q3.x; acc[7] += aj*q3.y;
    }

    int db = lane * 8;
    float4 b0 = *reinterpret_cast<const float4*>(bias + db);
    float4 b1 = *reinterpret_cast<const float4*>(bias + db + 4);
    float4 o0 = make_float4(fmaxf(acc[0]+b0.x, 0.f), fmaxf(acc[1]+b0.y, 0.f),
                            fmaxf(acc[2]+b0.z, 0.f), fmaxf(acc[3]+b0.w, 0.f));
    float4 o1 = make_float4(fmaxf(acc[4]+b1.x, 0.f), fmaxf(acc[5]+b1.y, 0.f),
                            fmaxf(acc[6]+b1.z, 0.f), fmaxf(acc[7]+b1.w, 0.f));
    float* dst = out + (long)v*(NH*HID) + db;
    *reinterpret_cast<float4*>(dst)     = o0;
    *reinterpret_cast<float4*>(dst + 4) = o1;
}

// -------- layer-2 aggregation: one warp per target (1 head), contiguous ------
__global__ void agg2c_kernel(const __half* __restrict__ f, const float* __restrict__ el,
                             const float* __restrict__ er, const float* __restrict__ bias,
                             float* __restrict__ out) {
    int i    = (blockIdx.x * blockDim.x + threadIdx.x) >> 5;
    int lane = threadIdx.x & 31;
    if (i >= NT1) return;

    float erv = er[NT1*DEG + i];
    float e = -1e30f;
    if (lane < DEG) {
        float x = el[i*DEG + lane] + erv;
        e = x > 0.f ? x : 0.2f * x;
    }
    float m = e;
    #pragma unroll
    for (int o = 8; o > 0; o >>= 1) m = fmaxf(m, __shfl_xor_sync(~0u, m, o, 16));
    float ex = (lane < DEG) ? __expf(e - m) : 0.f;
    float sm = ex;
    #pragma unroll
    for (int o = 8; o > 0; o >>= 1) sm += __shfl_xor_sync(~0u, sm, o, 16);
    float alpha = ex / sm;

    int half_ = lane >> 4;
    int dl    = lane & 15;
    const char* base = reinterpret_cast<const char*>(f) + (long)i*DEG*(HID*2) + dl*8;
    float4 acc = make_float4(0.f, 0.f, 0.f, 0.f);
    #pragma unroll
    for (int j = 0; j < DEG/2; j++) {
        int   eidx = 2*j + half_;
        float aj = __shfl_sync(~0u, alpha, eidx);
        uint2 raw = *reinterpret_cast<const uint2*>(base + eidx*(HID*2));
        float2 f0 = __half22float2(*reinterpret_cast<__half2*>(&raw.x));
        float2 f1 = __half22float2(*reinterpret_cast<__half2*>(&raw.y));
        acc.x += aj * f0.x;
        acc.y += aj * f0.y;
        acc.z += aj * f1.x;
        acc.w += aj * f1.y;
    }
    acc.x += __shfl_xor_sync(~0u, acc.x, 16);
    acc.y += __shfl_xor_sync(~0u, acc.y, 16);
    acc.z += __shfl_xor_sync(~0u, acc.z, 16);
    acc.w += __shfl_xor_sync(~0u, acc.w, 16);
    if (half_ == 0) {
        int d = dl * 4;
        float4 b4 = *reinterpret_cast<const float4*>(&bias[d]);
        float4 o4 = make_float4(acc.x + b4.x, acc.y + b4.y, acc.z + b4.z, acc.w + b4.w);
        *reinterpret_cast<float4*>(&out[(long)i*HID + d]) = o4;
    }
}

// ---------------- scores, labels, per-row loss ----------------
__global__ void score_kernel(const float* __restrict__ h2loc, float* __restrict__ out) {
    int i = blockIdx.x;
    int d = threadIdx.x;
    float su = h2loc[(long)i * HID + d];
    float si = h2loc[(long)(BATCH + i) * HID + d];
    float sc = su * si;
    out[1 + i*BATCH + d] = sc;
    out[1 + BATCH*BATCH + i*BATCH + d] = (i == d) ? 1.f : 0.f;

    __shared__ float buf[BATCH];
    __shared__ float diag;
    if (d == i) diag = sc;
    buf[d] = sc;
    __syncthreads();
    for (int st = 32; st > 0; st >>= 1) {
        if (d < st) buf[d] = fmaxf(buf[d], buf[d + st]);
        __syncthreads();
    }
    float mx = buf[0];
    __syncthreads();
    buf[d] = expf(sc - mx);
    __syncthreads();
    for (int st = 32; st > 0; st >>= 1) {
        if (d < st) buf[d] += buf[d + st];
        __syncthreads();
    }
    if (d == 0) {
        float lse = mx + logf(buf[0]);
        g_loss[i] = lse - diag;
    }
}

__global__ void finalize_kernel(float* __restrict__ out) {
    if (threadIdx.x == 0) {
        float s = 0.f;
        for (int i = 0; i < BATCH; i++) s += g_loss[i];
        out[0] = s / (float)BATCH;
    }
}

// ---------------- launcher ----------------
extern "C" void kernel_launch(void* const* d_in, const int* in_sizes, int n_in,
                              void* d_out, int out_size) {
    const int*   feat_ids = (const int*)  d_in[0];
    const int*   src      = (const int*)  d_in[1];
    const int*   user_ids = (const int*)  d_in[3];
    const int*   item_ids = (const int*)  d_in[4];
    const float* emb      = (const float*)d_in[5];
    const float* W1       = (const float*)d_in[6];
    const float* a_l1     = (const float*)d_in[7];
    const float* a_r1     = (const float*)d_in[8];
    const float* b1       = (const float*)d_in[9];
    const float* W2       = (const float*)d_in[10];
    const float* a_l2     = (const float*)d_in[11];
    const float* a_r2     = (const float*)d_in[12];
    const float* b2       = (const float*)d_in[13];
    float* out = (float*)d_out;

    int *ulist, *ucount;
    __half *f1loc, *f2loc;
    float *el1, *er1, *h1loc, *el2, *er2, *h2loc;
    cudaGetSymbolAddress((void**)&ulist,  g_ulist);
    cudaGetSymbolAddress((void**)&ucount, g_ucount);
    cudaGetSymbolAddress((void**)&f1loc,  g_f1loc);
    cudaGetSymbolAddress((void**)&el1,    g_el1loc);
    cudaGetSymbolAddress((void**)&er1,    g_er1loc);
    cudaGetSymbolAddress((void**)&h1loc,  g_h1loc);
    cudaGetSymbolAddress((void**)&f2loc,  g_f2loc);
    cudaGetSymbolAddress((void**)&el2,    g_el2loc);
    cudaGetSymbolAddress((void**)&er2,    g_er2loc);
    cudaGetSymbolAddress((void**)&h2loc,  g_h2loc);

    // index construction
    clear_marks<<<(NND + 511)/512, 512>>>();
    build_s1<<<(NS1 + 255)/256, 256>>>(src, user_ids, item_ids);
    mark_kernel<<<(NS0 + 255)/256, 256>>>(src, feat_ids);
    compact_kernel<<<(NND + 255)/256, 256>>>();
    lrow_kernel<<<(NS0 + 255)/256, 256>>>();

    // layer 1 GEMM over unique feat rows (dynamic count <= NS0)
    gemm_fused<64,256,16,4><<<(NS0 + 63)/64, 256>>>(
        emb, ulist, W1, a_l1, a_r1, f1loc, el1, er1, NS0, ucount, IN_F);
    agg1c_kernel<<<(NS1*32 + 255)/256, 256>>>(f1loc, el1, er1, b1, h1loc);

    // layer 2 GEMM over 2,176 local rows
    gemm_fused<128,64,32,1><<<NS1/128, 128>>>(
        h1loc, nullptr, W2, a_l2, a_r2, f2loc, el2, er2, NS1, nullptr, NH*HID);
    agg2c_kernel<<<(NT1*32)/256, 256>>>(f2loc, el2, er2, b2, h2loc);

    score_kernel<<<BATCH, BATCH>>>(h2loc, out);
    finalize_kernel<<<1, 32>>>(out);
}

// round 11
// speedup vs baseline: 2.7772x; 1.0660x over previous
#include <cuda_runtime.h>
#include <cuda_fp16.h>

// ---------------- problem constants ----------------
#define NND   50000
#define DEG   16
#define IN_F  128
#define HID   64
#define NH    4
#define BATCH 64

// compacted sizes
#define NT1   128                 // targets = [uid(64), iid(64)]
#define NS1   (NT1*DEG + NT1)     // 2176 rows where h1/f2 needed
#define NE1   (NS1*DEG)           // 34816 layer-1 edge slots
#define NS0   (NE1 + NS1)         // 36992 layer-0 row slots (before dedup)

typedef unsigned long long ull;

// ---------------- scratch ----------------
__device__ int    g_S1[NS1];            // global node id per local layer-1 row
__device__ int    g_mark[NND];          // feat-id -> slot+1 (0 = unused)
__device__ int    g_fid[NS0];           // feat id per layer-0 slot
__device__ int    g_lrow[NS0];          // layer-0 slot -> unique f1 row
__device__ int    g_ulist[NS0];         // unique feat ids (GEMM1 gather index)
__device__ int    g_ucount;
__device__ __half g_f1loc[NS0*NH*HID];  // unique rows x 256 fp16
__device__ float  g_el1loc[NS0*NH];
__device__ float  g_er1loc[NS0*NH];
__device__ float  g_h1loc[NS1*NH*HID];  // 2176 x 256 fp32
__device__ __half g_f2loc[NS1*HID];     // 2176 x 64 fp16
__device__ float  g_el2loc[NS1];
__device__ float  g_er2loc[NS1];
__device__ float  g_h2loc[NT1*HID];     // 128 x 64

// ---------------- packed f32x2 helpers ----------------
__device__ __forceinline__ ull pack_dup(float x) {
    ull r; asm("mov.b64 %0, {%1, %1};" : "=l"(r) : "f"(x)); return r;
}
__device__ __forceinline__ void ffma2(ull& acc, ull a, ull b) {
    asm("fma.rn.f32x2 %0, %1, %2, %0;" : "+l"(acc) : "l"(a), "l"(b));
}
__device__ __forceinline__ float2 unpack2(ull v) {
    float2 f; asm("mov.b64 {%0, %1}, %2;" : "=f"(f.x), "=f"(f.y) : "l"(v)); return f;
}

// ---------------- index building ----------------
__device__ __forceinline__ int target_of(int x, const int* uid, const int* iid) {
    return (x < BATCH) ? uid[x] : iid[x - BATCH];
}
// fused: clear marks + build S1 (independent element-wise work)
__global__ void init_kernel(const int* __restrict__ src, const int* __restrict__ uid,
                            const int* __restrict__ iid) {
    int i = blockIdx.x*blockDim.x + threadIdx.x;
    if (i < NND) g_mark[i] = 0;
    if (i == 0)  g_ucount = 0;
    if (i < NS1) {
        if (i < NT1*DEG) {
            int t = target_of(i >> 4, uid, iid);
            g_S1[i] = src[t*DEG + (i & 15)];
        } else {
            g_S1[i] = target_of(i - NT1*DEG, uid, iid);
        }
    }
}
__global__ void mark_kernel(const int* __restrict__ src, const int* __restrict__ feat_ids) {
    int p = blockIdx.x*blockDim.x + threadIdx.x;
    if (p >= NS0) return;
    int s;
    if (p < NE1) {
        int u = g_S1[p >> 4];
        s = src[u*DEG + (p & 15)];
    } else {
        s = g_S1[p - NE1];
    }
    int fid = feat_ids[s];
    g_fid[p] = fid;
    g_mark[fid] = 1;
}
// warp-aggregated compaction: one atomic per warp
__global__ void compact_kernel() {
    int v    = blockIdx.x*blockDim.x + threadIdx.x;
    int lane = threadIdx.x & 31;
    bool act = (v < NND) && (g_mark[v] != 0);
    unsigned mask = __ballot_sync(~0u, act);
    int cnt = __popc(mask);
    int base = 0;
    if (lane == 0 && cnt) base = atomicAdd(&g_ucount, cnt);
    base = __shfl_sync(~0u, base, 0);
    if (act) {
        int slot = base + __popc(mask & ((1u << lane) - 1));
        g_ulist[slot] = v;
        g_mark[v] = slot + 1;
    }
}
__global__ void lrow_kernel() {
    int p = blockIdx.x*blockDim.x + threadIdx.x;
    if (p >= NS0) return;
    g_lrow[p] = g_mark[g_fid[p]] - 1;
}

// ---------------- GEMM with 2-D warp tiling + fused attention dots ----------
// Mdyn != nullptr -> row count read from device (dedup'd count)
template<int BM,int BN,int BK,int NHh>
__global__ __launch_bounds__((BM/8)*(BN/8))
void gemm_fused(const float* __restrict__ A, const int* __restrict__ gidx,
                const float* __restrict__ B,
                const float* __restrict__ al, const float* __restrict__ ar,
                __half* __restrict__ Ch, float* __restrict__ el, float* __restrict__ er,
                int M, const int* __restrict__ Mdyn, int K) {
    if (Mdyn) M = *Mdyn;
    const int m0 = blockIdx.x * BM;
    if (m0 >= M) return;

    constexpr int TM = 8, TN = 8;
    constexpr int NT = (BM/TM)*(BN/TN);
    constexpr int NWARP = NT/32;
    constexpr int WN = BN/64;
    constexpr int WM = NWARP/WN;
    static_assert(WM*32 == BM && WN*64 == BN, "warp tiling");
    __shared__ float As[BK][BM];
    __shared__ float Bs[BK][BN];
    const int tid  = threadIdx.x;
    const int warp = tid >> 5;
    const int lane = tid & 31;
    const int wm = warp % WM, wn = warp / WM;
    const int lr = lane >> 3, lc = lane & 7;
    const int ty = wm*4 + lr;
    const int tx = wn*8 + lc;

    constexpr int A_F4 = BM*BK/4;
    constexpr int A_IT = A_F4 / NT;
    static_assert(A_IT >= 1 && A_F4 % NT == 0, "A tiling");
    long arow[A_IT];
    #pragma unroll
    for (int r = 0; r < A_IT; r++) {
        int idx = tid + r*NT;
        int mA  = idx / (BK/4);
        int gm  = m0 + mA;
        int row = (gm < M) ? (gidx ? gidx[gm] : gm) : (gidx ? gidx[0] : 0);
        arow[r] = (long)row * K;
    }
    constexpr int B_F4 = BK*BN/4;
    constexpr int B_IT = B_F4 / NT;
    static_assert(B_IT >= 1 && B_F4 % NT == 0, "B tiling");

    ull acc2[TM/2][TN];
    #pragma unroll
    for (int i = 0; i < TM/2; i++)
        #pragma unroll
        for (int j = 0; j < TN; j++) acc2[i][j] = 0ull;

    for (int k0 = 0; k0 < K; k0 += BK) {
        #pragma unroll
        for (int r = 0; r < A_IT; r++) {
            int idx = tid + r*NT;
            int mA  = idx / (BK/4);
            int kq  = idx % (BK/4);
            float4 v = *reinterpret_cast<const float4*>(A + arow[r] + k0 + kq*4);
            As[kq*4+0][mA] = v.x;
            As[kq*4+1][mA] = v.y;
            As[kq*4+2][mA] = v.z;
            As[kq*4+3][mA] = v.w;
        }
        #pragma unroll
        for (int r = 0; r < B_IT; r++) {
            int idx = tid + r*NT;
            int kB  = idx / (BN/4);
            int nq  = idx % (BN/4);
            float4 v = *reinterpret_cast<const float4*>(B + (long)(k0+kB)*BN + nq*4);
            *reinterpret_cast<float4*>(&Bs[kB][nq*4]) = v;
        }
        __syncthreads();
        #pragma unroll
        for (int k = 0; k < BK; k++) {
            ull a2[TM/2];
            const ull* ap = reinterpret_cast<const ull*>(&As[k][ty*TM]);
            #pragma unroll
            for (int i = 0; i < TM/2; i++) a2[i] = ap[i];
            float4 blo = *reinterpret_cast<const float4*>(&Bs[k][tx*TN]);
            float4 bhi = *reinterpret_cast<const float4*>(&Bs[k][tx*TN+4]);
            ull b2[TN];
            b2[0]=pack_dup(blo.x); b2[1]=pack_dup(blo.y);
            b2[2]=pack_dup(blo.z); b2[3]=pack_dup(blo.w);
            b2[4]=pack_dup(bhi.x); b2[5]=pack_dup(bhi.y);
            b2[6]=pack_dup(bhi.z); b2[7]=pack_dup(bhi.w);
            #pragma unroll
            for (int i = 0; i < TM/2; i++)
                #pragma unroll
                for (int j = 0; j < TN; j++) ffma2(acc2[i][j], a2[i], b2[j]);
        }
        __syncthreads();
    }

    float acc[TM][TN];
    #pragma unroll
    for (int i = 0; i < TM/2; i++)
        #pragma unroll
        for (int j = 0; j < TN; j++) {
            float2 p = unpack2(acc2[i][j]);
            acc[2*i  ][j] = p.x;
            acc[2*i+1][j] = p.y;
        }

    float alr[TN], arr[TN];
    #pragma unroll
    for (int j = 0; j < TN; j++) { int n = tx*TN + j; alr[j] = al[n]; arr[j] = ar[n]; }

    #pragma unroll
    for (int i = 0; i < TM; i++) {
        int gm = m0 + ty*TM + i;
        float sl = 0.f, sr = 0.f;
        #pragma unroll
        for (int j = 0; j < TN; j++) { sl += acc[i][j]*alr[j]; sr += acc[i][j]*arr[j]; }
        #pragma unroll
        for (int o = 1; o < 8; o <<= 1) {
            sl += __shfl_xor_sync(~0u, sl, o);
            sr += __shfl_xor_sync(~0u, sr, o);
        }
        if (gm < M) {
            __half2 p0 = __floats2half2_rn(acc[i][0], acc[i][1]);
            __half2 p1 = __floats2half2_rn(acc[i][2], acc[i][3]);
            __half2 p2 = __floats2half2_rn(acc[i][4], acc[i][5]);
            __half2 p3 = __floats2half2_rn(acc[i][6], acc[i][7]);
            uint4 w;
            w.x = *reinterpret_cast<unsigned*>(&p0);
            w.y = *reinterpret_cast<unsigned*>(&p1);
            w.z = *reinterpret_cast<unsigned*>(&p2);
            w.w = *reinterpret_cast<unsigned*>(&p3);
            *reinterpret_cast<uint4*>(&Ch[(long)gm*BN + tx*TN]) = w;
            if (lc == 0) {
                el[(long)gm*NHh + wn] = sl;
                er[(long)gm*NHh + wn] = sr;
            }
        }
    }
}

// -------- layer-1 aggregation: one warp per local node (4 heads), lrow gather --
__global__ void agg1c_kernel(const __half* __restrict__ f, const float* __restrict__ el,
                             const float* __restrict__ er, const float* __restrict__ bias,
                             float* __restrict__ out) {
    int v    = (blockIdx.x * blockDim.x + threadIdx.x) >> 5;
    int lane = threadIdx.x & 31;
    if (v >= NS1) return;
    const int h    = lane & 3;
    const int eidx = lane >> 2;

    int ru = g_lrow[NE1 + v];
    float erv = er[ru*NH + h];
    int r0 = g_lrow[v*DEG + eidx];
    int r1 = g_lrow[v*DEG + eidx + 8];
    float x0 = el[r0*NH + h] + erv;
    float x1 = el[r1*NH + h] + erv;
    x0 = x0 > 0.f ? x0 : 0.2f * x0;
    x1 = x1 > 0.f ? x1 : 0.2f * x1;

    float m = fmaxf(x0, x1);
    m = fmaxf(m, __shfl_xor_sync(~0u, m, 4));
    m = fmaxf(m, __shfl_xor_sync(~0u, m, 8));
    m = fmaxf(m, __shfl_xor_sync(~0u, m, 16));
    float ex0 = __expf(x0 - m), ex1 = __expf(x1 - m);
    float sm = ex0 + ex1;
    sm += __shfl_xor_sync(~0u, sm, 4);
    sm += __shfl_xor_sync(~0u, sm, 8);
    sm += __shfl_xor_sync(~0u, sm, 16);
    float inv = __frcp_rn(sm);
    float a0 = ex0 * inv, a1 = ex1 * inv;
    int off0 = r0 * (NH*HID*2);
    int off1 = r1 * (NH*HID*2);

    const char* base = reinterpret_cast<const char*>(f) + lane*16;
    const int hl = lane >> 3;
    float acc[8];
    #pragma unroll
    for (int q = 0; q < 8; q++) acc[q] = 0.f;

    #pragma unroll
    for (int j = 0; j < DEG; j++) {
        int srcl = ((j & 7) << 2) + hl;
        int   oj = __shfl_sync(~0u, (j < 8) ? off0 : off1, srcl);
        float aj = __shfl_sync(~0u, (j < 8) ? a0  : a1,  srcl);
        uint4 raw = *reinterpret_cast<const uint4*>(base + oj);
        float2 q0 = __half22float2(*reinterpret_cast<__half2*>(&raw.x));
        float2 q1 = __half22float2(*reinterpret_cast<__half2*>(&raw.y));
        float2 q2 = __half22float2(*reinterpret_cast<__half2*>(&raw.z));
        float2 q3 = __half22float2(*reinterpret_cast<__half2*>(&raw.w));
        acc[0] += aj*q0.x; acc[1] += aj*q0.y;
        acc[2] += aj*q1.x; acc[3] += aj*q1.y;
        acc[4] += aj*q2.x; acc[5] += aj*q2.y;
        acc[6] += aj*q3.x; acc[7] += aj*q3.y;
    }

    int db = lane * 8;
    float4 b0 = *reinterpret_cast<const float4*>(bias + db);
    float4 b1 = *reinterpret_cast<const float4*>(bias + db + 4);
    float4 o0 = make_float4(fmaxf(acc[0]+b0.x, 0.f), fmaxf(acc[1]+b0.y, 0.f),
                            fmaxf(acc[2]+b0.z, 0.f), fmaxf(acc[3]+b0.w, 0.f));
    float4 o1 = make_float4(fmaxf(acc[4]+b1.x, 0.f), fmaxf(acc[5]+b1.y, 0.f),
                            fmaxf(acc[6]+b1.z, 0.f), fmaxf(acc[7]+b1.w, 0.f));
    float* dst = out + (long)v*(NH*HID) + db;
    *reinterpret_cast<float4*>(dst)     = o0;
    *reinterpret_cast<float4*>(dst + 4) = o1;
}

// -------- layer-2 aggregation: one warp per target (1 head), contiguous ------
__global__ void agg2c_kernel(const __half* __restrict__ f, const float* __restrict__ el,
                             const float* __restrict__ er, const float* __restrict__ bias,
                             float* __restrict__ out) {
    int i    = (blockIdx.x * blockDim.x + threadIdx.x) >> 5;
    int lane = threadIdx.x & 31;
    if (i >= NT1) return;

    float erv = er[NT1*DEG + i];
    float e = -1e30f;
    if (lane < DEG) {
        float x = el[i*DEG + lane] + erv;
        e = x > 0.f ? x : 0.2f * x;
    }
    float m = e;
    #pragma unroll
    for (int o = 8; o > 0; o >>= 1) m = fmaxf(m, __shfl_xor_sync(~0u, m, o, 16));
    float ex = (lane < DEG) ? __expf(e - m) : 0.f;
    float sm = ex;
    #pragma unroll
    for (int o = 8; o > 0; o >>= 1) sm += __shfl_xor_sync(~0u, sm, o, 16);
    float alpha = ex / sm;

    int half_ = lane >> 4;
    int dl    = lane & 15;
    const char* base = reinterpret_cast<const char*>(f) + (long)i*DEG*(HID*2) + dl*8;
    float4 acc = make_float4(0.f, 0.f, 0.f, 0.f);
    #pragma unroll
    for (int j = 0; j < DEG/2; j++) {
        int   eidx = 2*j + half_;
        float aj = __shfl_sync(~0u, alpha, eidx);
        uint2 raw = *reinterpret_cast<const uint2*>(base + eidx*(HID*2));
        float2 f0 = __half22float2(*reinterpret_cast<__half2*>(&raw.x));
        float2 f1 = __half22float2(*reinterpret_cast<__half2*>(&raw.y));
        acc.x += aj * f0.x;
        acc.y += aj * f0.y;
        acc.z += aj * f1.x;
        acc.w += aj * f1.y;
    }
    acc.x += __shfl_xor_sync(~0u, acc.x, 16);
    acc.y += __shfl_xor_sync(~0u, acc.y, 16);
    acc.z += __shfl_xor_sync(~0u, acc.z, 16);
    acc.w += __shfl_xor_sync(~0u, acc.w, 16);
    if (half_ == 0) {
        int d = dl * 4;
        float4 b4 = *reinterpret_cast<const float4*>(&bias[d]);
        float4 o4 = make_float4(acc.x + b4.x, acc.y + b4.y, acc.z + b4.z, acc.w + b4.w);
        *reinterpret_cast<float4*>(&out[(long)i*HID + d]) = o4;
    }
}

// ------- fused scores + labels + per-row loss + mean (single block) ---------
__global__ __launch_bounds__(1024)
void score_loss_kernel(const float* __restrict__ h2loc, float* __restrict__ out) {
    int lane = threadIdx.x & 31, warp = threadIdx.x >> 5;
    __shared__ float sloss[BATCH];
    #pragma unroll
    for (int rep = 0; rep < 2; rep++) {
        int i = warp*2 + rep;                      // row 0..63
        float su0 = h2loc[i*HID + lane];
        float su1 = h2loc[i*HID + lane + 32];
        float si0 = h2loc[(BATCH + i)*HID + lane];
        float si1 = h2loc[(BATCH + i)*HID + lane + 32];
        float sc0 = su0*si0, sc1 = su1*si1;
        out[1 + i*BATCH + lane]      = sc0;
        out[1 + i*BATCH + lane + 32] = sc1;
        out[1 + BATCH*BATCH + i*BATCH + lane]      = (i == lane)      ? 1.f : 0.f;
        out[1 + BATCH*BATCH + i*BATCH + lane + 32] = (i == lane + 32) ? 1.f : 0.f;
        float diag = (i < 32) ? __shfl_sync(~0u, sc0, i)
                              : __shfl_sync(~0u, sc1, i - 32);
        float m = fmaxf(sc0, sc1);
        #pragma unroll
        for (int o = 16; o; o >>= 1) m = fmaxf(m, __shfl_xor_sync(~0u, m, o));
        float s = expf(sc0 - m) + expf(sc1 - m);
        #pragma unroll
        for (int o = 16; o; o >>= 1) s += __shfl_xor_sync(~0u, s, o);
        if (lane == 0) sloss[i] = m + logf(s) - diag;
    }
    __syncthreads();
    if (warp == 0) {
        float s = sloss[lane] + sloss[lane + 32];
        #pragma unroll
        for (int o = 16; o; o >>= 1) s += __shfl_xor_sync(~0u, s, o);
        if (lane == 0) out[0] = s / (float)BATCH;
    }
}

// ---------------- launcher ----------------
extern "C" void kernel_launch(void* const* d_in, const int* in_sizes, int n_in,
                              void* d_out, int out_size) {
    const int*   feat_ids = (const int*)  d_in[0];
    const int*   src      = (const int*)  d_in[1];
    const int*   user_ids = (const int*)  d_in[3];
    const int*   item_ids = (const int*)  d_in[4];
    const float* emb      = (const float*)d_in[5];
    const float* W1       = (const float*)d_in[6];
    const float* a_l1     = (const float*)d_in[7];
    const float* a_r1     = (const float*)d_in[8];
    const float* b1       = (const float*)d_in[9];
    const float* W2       = (const float*)d_in[10];
    const float* a_l2     = (const float*)d_in[11];
    const float* a_r2     = (const float*)d_in[12];
    const float* b2       = (const float*)d_in[13];
    float* out = (float*)d_out;

    int *ulist, *ucount;
    __half *f1loc, *f2loc;
    float *el1, *er1, *h1loc, *el2, *er2, *h2loc;
    cudaGetSymbolAddress((void**)&ulist,  g_ulist);
    cudaGetSymbolAddress((void**)&ucount, g_ucount);
    cudaGetSymbolAddress((void**)&f1loc,  g_f1loc);
    cudaGetSymbolAddress((void**)&el1,    g_el1loc);
    cudaGetSymbolAddress((void**)&er1,    g_er1loc);
    cudaGetSymbolAddress((void**)&h1loc,  g_h1loc);
    cudaGetSymbolAddress((void**)&f2loc,  g_f2loc);
    cudaGetSymbolAddress((void**)&el2,    g_el2loc);
    cudaGetSymbolAddress((void**)&er2,    g_er2loc);
    cudaGetSymbolAddress((void**)&h2loc,  g_h2loc);

    // index construction (4 launches)
    init_kernel<<<(NND + 511)/512, 512>>>(src, user_ids, item_ids);
    mark_kernel<<<(NS0 + 255)/256, 256>>>(src, feat_ids);
    compact_kernel<<<(NND + 255)/256, 256>>>();
    lrow_kernel<<<(NS0 + 255)/256, 256>>>();

    // layer 1 GEMM over unique feat rows (dynamic count <= NS0), BM=64/BK=32
    gemm_fused<64,256,32,4><<<(NS0 + 63)/64, 256>>>(
        emb, ulist, W1, a_l1, a_r1, f1loc, el1, er1, NS0, ucount, IN_F);
    agg1c_kernel<<<(NS1*32 + 255)/256, 256>>>(f1loc, el1, er1, b1, h1loc);

    // layer 2 GEMM over 2,176 local rows, BM=64 (34 CTAs)
    gemm_fused<64,64,32,1><<<NS1/64, 64>>>(
        h1loc, nullptr, W2, a_l2, a_r2, f2loc, el2, er2, NS1, nullptr, NH*HID);
    agg2c_kernel<<<(NT1*32)/256, 256>>>(f2loc, el2, er2, b2, h2loc);

    score_loss_kernel<<<1, 1024>>>(h2loc, out);
}

// round 12
// speedup vs baseline: 2.8481x; 1.0255x over previous
#include <cuda_runtime.h>
#include <cuda_fp16.h>

// ---------------- problem constants ----------------
#define NND   50000
#define DEG   16
#define IN_F  128
#define HID   64
#define NH    4
#define BATCH 64

// compacted sizes
#define NT1   128                 // targets = [uid(64), iid(64)]
#define NS1   (NT1*DEG + NT1)     // 2176 rows where h1/f2 needed
#define NE1   (NS1*DEG)           // 34816 layer-1 edge slots
#define NS0   (NE1 + NS1)         // 36992 layer-0 row slots (before dedup)

typedef unsigned long long ull;

// ---------------- scratch ----------------
__device__ int    g_mark[NND];          // feat-id -> slot+1 (0 unused, -1 claimed)
__device__ int    g_fid[NS0];           // feat id per layer-0 slot
__device__ int    g_ulist[NS0];         // unique feat ids (GEMM1 gather index)
__device__ int    g_ucount;
__device__ __half g_f1loc[NS0*NH*HID];  // unique rows x 256 fp16
__device__ float  g_el1loc[NS0*NH];
__device__ float  g_er1loc[NS0*NH];
__device__ float  g_h1loc[NS1*NH*HID];  // 2176 x 256 fp32
__device__ __half g_f2loc[NS1*HID];     // 2176 x 64 fp16
__device__ float  g_el2loc[NS1];
__device__ float  g_er2loc[NS1];
__device__ float  g_h2loc[NT1*HID];     // 128 x 64

// ---------------- packed f32x2 helpers ----------------
__device__ __forceinline__ ull pack_dup(float x) {
    ull r; asm("mov.b64 %0, {%1, %1};" : "=l"(r) : "f"(x)); return r;
}
__device__ __forceinline__ void ffma2(ull& acc, ull a, ull b) {
    asm("fma.rn.f32x2 %0, %1, %2, %0;" : "+l"(acc) : "l"(a), "l"(b));
}
__device__ __forceinline__ float2 unpack2(ull v) {
    float2 f; asm("mov.b64 {%0, %1}, %2;" : "=f"(f.x), "=f"(f.y) : "l"(v)); return f;
}

// ---------------- index building (2 launches) ----------------
__device__ __forceinline__ int target_of(int x, const int* uid, const int* iid) {
    return (x < BATCH) ? uid[x] : iid[x - BATCH];
}
__global__ void init_kernel() {
    int i = blockIdx.x*blockDim.x + threadIdx.x;
    if (i < NND) g_mark[i] = 0;
    if (i == 0)  g_ucount = 0;
}
// per layer-0 slot: compute source node inline, mark + warp-aggregated compact
__global__ void mark_compact(const int* __restrict__ src, const int* __restrict__ feat_ids,
                             const int* __restrict__ uid, const int* __restrict__ iid) {
    int p    = blockIdx.x*blockDim.x + threadIdx.x;
    int lane = threadIdx.x & 31;
    int fid  = 0;
    bool win = false;
    if (p < NS0) {
        // local layer-1 row index this slot belongs to
        int i = (p < NE1) ? (p >> 4) : (p - NE1);
        int u;
        if (i < NT1*DEG) {
            int t = target_of(i >> 4, uid, iid);
            u = src[t*DEG + (i & 15)];
        } else {
            u = target_of(i - NT1*DEG, uid, iid);
        }
        int s = (p < NE1) ? src[u*DEG + (p & 15)] : u;
        fid = feat_ids[s];
        g_fid[p] = fid;
        win = (atomicCAS(&g_mark[fid], 0, -1) == 0);
    }
    unsigned mask = __ballot_sync(~0u, win);
    int cnt = __popc(mask);
    int base = 0;
    if (lane == 0 && cnt) base = atomicAdd(&g_ucount, cnt);
    base = __shfl_sync(~0u, base, 0);
    if (win) {
        int slot = base + __popc(mask & ((1u << lane) - 1));
        g_ulist[slot] = fid;
        g_mark[fid] = slot + 1;
    }
}

// ---------------- GEMM with 2-D warp tiling + fused attention dots ----------
template<int BM,int BN,int BK,int NHh>
__global__ __launch_bounds__((BM/8)*(BN/8))
void gemm_fused(const float* __restrict__ A, const int* __restrict__ gidx,
                const float* __restrict__ B,
                const float* __restrict__ al, const float* __restrict__ ar,
                __half* __restrict__ Ch, float* __restrict__ el, float* __restrict__ er,
                int M, const int* __restrict__ Mdyn, int K) {
    if (Mdyn) M = *Mdyn;
    const int m0 = blockIdx.x * BM;
    if (m0 >= M) return;

    constexpr int TM = 8, TN = 8;
    constexpr int NT = (BM/TM)*(BN/TN);
    constexpr int NWARP = NT/32;
    constexpr int WN = BN/64;
    constexpr int WM = NWARP/WN;
    static_assert(WM*32 == BM && WN*64 == BN, "warp tiling");
    __shared__ float As[BK][BM];
    __shared__ float Bs[BK][BN];
    const int tid  = threadIdx.x;
    const int warp = tid >> 5;
    const int lane = tid & 31;
    const int wm = warp % WM, wn = warp / WM;
    const int lr = lane >> 3, lc = lane & 7;
    const int ty = wm*4 + lr;
    const int tx = wn*8 + lc;

    constexpr int A_F4 = BM*BK/4;
    constexpr int A_IT = A_F4 / NT;
    static_assert(A_IT >= 1 && A_F4 % NT == 0, "A tiling");
    long arow[A_IT];
    #pragma unroll
    for (int r = 0; r < A_IT; r++) {
        int idx = tid + r*NT;
        int mA  = idx / (BK/4);
        int gm  = m0 + mA;
        int row = (gm < M) ? (gidx ? gidx[gm] : gm) : (gidx ? gidx[0] : 0);
        arow[r] = (long)row * K;
    }
    constexpr int B_F4 = BK*BN/4;
    constexpr int B_IT = B_F4 / NT;
    static_assert(B_IT >= 1 && B_F4 % NT == 0, "B tiling");

    ull acc2[TM/2][TN];
    #pragma unroll
    for (int i = 0; i < TM/2; i++)
        #pragma unroll
        for (int j = 0; j < TN; j++) acc2[i][j] = 0ull;

    for (int k0 = 0; k0 < K; k0 += BK) {
        #pragma unroll
        for (int r = 0; r < A_IT; r++) {
            int idx = tid + r*NT;
            int mA  = idx / (BK/4);
            int kq  = idx % (BK/4);
            float4 v = *reinterpret_cast<const float4*>(A + arow[r] + k0 + kq*4);
            As[kq*4+0][mA] = v.x;
            As[kq*4+1][mA] = v.y;
            As[kq*4+2][mA] = v.z;
            As[kq*4+3][mA] = v.w;
        }
        #pragma unroll
        for (int r = 0; r < B_IT; r++) {
            int idx = tid + r*NT;
            int kB  = idx / (BN/4);
            int nq  = idx % (BN/4);
            float4 v = *reinterpret_cast<const float4*>(B + (long)(k0+kB)*BN + nq*4);
            *reinterpret_cast<float4*>(&Bs[kB][nq*4]) = v;
        }
        __syncthreads();
        #pragma unroll
        for (int k = 0; k < BK; k++) {
            ull a2[TM/2];
            const ull* ap = reinterpret_cast<const ull*>(&As[k][ty*TM]);
            #pragma unroll
            for (int i = 0; i < TM/2; i++) a2[i] = ap[i];
            float4 blo = *reinterpret_cast<const float4*>(&Bs[k][tx*TN]);
            float4 bhi = *reinterpret_cast<const float4*>(&Bs[k][tx*TN+4]);
            ull b2[TN];
            b2[0]=pack_dup(blo.x); b2[1]=pack_dup(blo.y);
            b2[2]=pack_dup(blo.z); b2[3]=pack_dup(blo.w);
            b2[4]=pack_dup(bhi.x); b2[5]=pack_dup(bhi.y);
            b2[6]=pack_dup(bhi.z); b2[7]=pack_dup(bhi.w);
            #pragma unroll
            for (int i = 0; i < TM/2; i++)
                #pragma unroll
                for (int j = 0; j < TN; j++) ffma2(acc2[i][j], a2[i], b2[j]);
        }
        __syncthreads();
    }

    float acc[TM][TN];
    #pragma unroll
    for (int i = 0; i < TM/2; i++)
        #pragma unroll
        for (int j = 0; j < TN; j++) {
            float2 p = unpack2(acc2[i][j]);
            acc[2*i  ][j] = p.x;
            acc[2*i+1][j] = p.y;
        }

    float alr[TN], arr[TN];
    #pragma unroll
    for (int j = 0; j < TN; j++) { int n = tx*TN + j; alr[j] = al[n]; arr[j] = ar[n]; }

    #pragma unroll
    for (int i = 0; i < TM; i++) {
        int gm = m0 + ty*TM + i;
        float sl = 0.f, sr = 0.f;
        #pragma unroll
        for (int j = 0; j < TN; j++) { sl += acc[i][j]*alr[j]; sr += acc[i][j]*arr[j]; }
        #pragma unroll
        for (int o = 1; o < 8; o <<= 1) {
            sl += __shfl_xor_sync(~0u, sl, o);
            sr += __shfl_xor_sync(~0u, sr, o);
        }
        if (gm < M) {
            __half2 p0 = __floats2half2_rn(acc[i][0], acc[i][1]);
            __half2 p1 = __floats2half2_rn(acc[i][2], acc[i][3]);
            __half2 p2 = __floats2half2_rn(acc[i][4], acc[i][5]);
            __half2 p3 = __floats2half2_rn(acc[i][6], acc[i][7]);
            uint4 w;
            w.x = *reinterpret_cast<unsigned*>(&p0);
            w.y = *reinterpret_cast<unsigned*>(&p1);
            w.z = *reinterpret_cast<unsigned*>(&p2);
            w.w = *reinterpret_cast<unsigned*>(&p3);
            *reinterpret_cast<uint4*>(&Ch[(long)gm*BN + tx*TN]) = w;
            if (lc == 0) {
                el[(long)gm*NHh + wn] = sl;
                er[(long)gm*NHh + wn] = sr;
            }
        }
    }
}

// -------- layer-1 aggregation: one warp per local node (4 heads) -------------
// lrow computed inline: g_mark[g_fid[slot]] - 1
__global__ void agg1c_kernel(const __half* __restrict__ f, const float* __restrict__ el,
                             const float* __restrict__ er, const float* __restrict__ bias,
                             float* __restrict__ out) {
    int v    = (blockIdx.x * blockDim.x + threadIdx.x) >> 5;
    int lane = threadIdx.x & 31;
    if (v >= NS1) return;
    const int h    = lane & 3;
    const int eidx = lane >> 2;

    int ru = g_mark[g_fid[NE1 + v]] - 1;
    float erv = er[ru*NH + h];
    int r0 = g_mark[g_fid[v*DEG + eidx]] - 1;
    int r1 = g_mark[g_fid[v*DEG + eidx + 8]] - 1;
    float x0 = el[r0*NH + h] + erv;
    float x1 = el[r1*NH + h] + erv;
    x0 = x0 > 0.f ? x0 : 0.2f * x0;
    x1 = x1 > 0.f ? x1 : 0.2f * x1;

    float m = fmaxf(x0, x1);
    m = fmaxf(m, __shfl_xor_sync(~0u, m, 4));
    m = fmaxf(m, __shfl_xor_sync(~0u, m, 8));
    m = fmaxf(m, __shfl_xor_sync(~0u, m, 16));
    float ex0 = __expf(x0 - m), ex1 = __expf(x1 - m);
    float sm = ex0 + ex1;
    sm += __shfl_xor_sync(~0u, sm, 4);
    sm += __shfl_xor_sync(~0u, sm, 8);
    sm += __shfl_xor_sync(~0u, sm, 16);
    float inv = __frcp_rn(sm);
    float a0 = ex0 * inv, a1 = ex1 * inv;
    int off0 = r0 * (NH*HID*2);
    int off1 = r1 * (NH*HID*2);

    const char* base = reinterpret_cast<const char*>(f) + lane*16;
    const int hl = lane >> 3;
    float acc[8];
    #pragma unroll
    for (int q = 0; q < 8; q++) acc[q] = 0.f;

    #pragma unroll
    for (int j = 0; j < DEG; j++) {
        int srcl = ((j & 7) << 2) + hl;
        int   oj = __shfl_sync(~0u, (j < 8) ? off0 : off1, srcl);
        float aj = __shfl_sync(~0u, (j < 8) ? a0  : a1,  srcl);
        uint4 raw = *reinterpret_cast<const uint4*>(base + oj);
        float2 q0 = __half22float2(*reinterpret_cast<__half2*>(&raw.x));
        float2 q1 = __half22float2(*reinterpret_cast<__half2*>(&raw.y));
        float2 q2 = __half22float2(*reinterpret_cast<__half2*>(&raw.z));
        float2 q3 = __half22float2(*reinterpret_cast<__half2*>(&raw.w));
        acc[0] += aj*q0.x; acc[1] += aj*q0.y;
        acc[2] += aj*q1.x; acc[3] += aj*q1.y;
        acc[4] += aj*q2.x; acc[5] += aj*q2.y;
        acc[6] += aj*q3.x; acc[7] += aj*q3.y;
    }

    int db = lane * 8;
    float4 b0 = *reinterpret_cast<const float4*>(bias + db);
    float4 b1 = *reinterpret_cast<const float4*>(bias + db + 4);
    float4 o0 = make_float4(fmaxf(acc[0]+b0.x, 0.f), fmaxf(acc[1]+b0.y, 0.f),
                            fmaxf(acc[2]+b0.z, 0.f), fmaxf(acc[3]+b0.w, 0.f));
    float4 o1 = make_float4(fmaxf(acc[4]+b1.x, 0.f), fmaxf(acc[5]+b1.y, 0.f),
                            fmaxf(acc[6]+b1.z, 0.f), fmaxf(acc[7]+b1.w, 0.f));
    float* dst = out + (long)v*(NH*HID) + db;
    *reinterpret_cast<float4*>(dst)     = o0;
    *reinterpret_cast<float4*>(dst + 4) = o1;
}

// -------- layer-2 aggregation: one warp per target (1 head), contiguous ------
__global__ void agg2c_kernel(const __half* __restrict__ f, const float* __restrict__ el,
                             const float* __restrict__ er, const float* __restrict__ bias,
                             float* __restrict__ out) {
    int i    = (blockIdx.x * blockDim.x + threadIdx.x) >> 5;
    int lane = threadIdx.x & 31;
    if (i >= NT1) return;

    float erv = er[NT1*DEG + i];
    float e = -1e30f;
    if (lane < DEG) {
        float x = el[i*DEG + lane] + erv;
        e = x > 0.f ? x : 0.2f * x;
    }
    float m = e;
    #pragma unroll
    for (int o = 8; o > 0; o >>= 1) m = fmaxf(m, __shfl_xor_sync(~0u, m, o, 16));
    float ex = (lane < DEG) ? __expf(e - m) : 0.f;
    float sm = ex;
    #pragma unroll
    for (int o = 8; o > 0; o >>= 1) sm += __shfl_xor_sync(~0u, sm, o, 16);
    float alpha = ex / sm;

    int half_ = lane >> 4;
    int dl    = lane & 15;
    const char* base = reinterpret_cast<const char*>(f) + (long)i*DEG*(HID*2) + dl*8;
    float4 acc = make_float4(0.f, 0.f, 0.f, 0.f);
    #pragma unroll
    for (int j = 0; j < DEG/2; j++) {
        int   eidx = 2*j + half_;
        float aj = __shfl_sync(~0u, alpha, eidx);
        uint2 raw = *reinterpret_cast<const uint2*>(base + eidx*(HID*2));
        float2 f0 = __half22float2(*reinterpret_cast<__half2*>(&raw.x));
        float2 f1 = __half22float2(*reinterpret_cast<__half2*>(&raw.y));
        acc.x += aj * f0.x;
        acc.y += aj * f0.y;
        acc.z += aj * f1.x;
        acc.w += aj * f1.y;
    }
    acc.x += __shfl_xor_sync(~0u, acc.x, 16);
    acc.y += __shfl_xor_sync(~0u, acc.y, 16);
    acc.z += __shfl_xor_sync(~0u, acc.z, 16);
    acc.w += __shfl_xor_sync(~0u, acc.w, 16);
    if (half_ == 0) {
        int d = dl * 4;
        float4 b4 = *reinterpret_cast<const float4*>(&bias[d]);
        float4 o4 = make_float4(acc.x + b4.x, acc.y + b4.y, acc.z + b4.z, acc.w + b4.w);
        *reinterpret_cast<float4*>(&out[(long)i*HID + d]) = o4;
    }
}

// ------- fused scores + labels + per-row loss + mean (single block) ---------
__global__ __launch_bounds__(1024)
void score_loss_kernel(const float* __restrict__ h2loc, float* __restrict__ out) {
    int lane = threadIdx.x & 31, warp = threadIdx.x >> 5;
    __shared__ float sloss[BATCH];
    #pragma unroll
    for (int rep = 0; rep < 2; rep++) {
        int i = warp*2 + rep;
        float su0 = h2loc[i*HID + lane];
        float su1 = h2loc[i*HID + lane + 32];
        float si0 = h2loc[(BATCH + i)*HID + lane];
        float si1 = h2loc[(BATCH + i)*HID + lane + 32];
        float sc0 = su0*si0, sc1 = su1*si1;
        out[1 + i*BATCH + lane]      = sc0;
        out[1 + i*BATCH + lane + 32] = sc1;
        out[1 + BATCH*BATCH + i*BATCH + lane]      = (i == lane)      ? 1.f : 0.f;
        out[1 + BATCH*BATCH + i*BATCH + lane + 32] = (i == lane + 32) ? 1.f : 0.f;
        float diag = (i < 32) ? __shfl_sync(~0u, sc0, i)
                              : __shfl_sync(~0u, sc1, i - 32);
        float m = fmaxf(sc0, sc1);
        #pragma unroll
        for (int o = 16; o; o >>= 1) m = fmaxf(m, __shfl_xor_sync(~0u, m, o));
        float s = expf(sc0 - m) + expf(sc1 - m);
        #pragma unroll
        for (int o = 16; o; o >>= 1) s += __shfl_xor_sync(~0u, s, o);
        if (lane == 0) sloss[i] = m + logf(s) - diag;
    }
    __syncthreads();
    if (warp == 0) {
        float s = sloss[lane] + sloss[lane + 32];
        #pragma unroll
        for (int o = 16; o; o >>= 1) s += __shfl_xor_sync(~0u, s, o);
        if (lane == 0) out[0] = s / (float)BATCH;
    }
}

// ---------------- launcher ----------------
extern "C" void kernel_launch(void* const* d_in, const int* in_sizes, int n_in,
                              void* d_out, int out_size) {
    const int*   feat_ids = (const int*)  d_in[0];
    const int*   src      = (const int*)  d_in[1];
    const int*   user_ids = (const int*)  d_in[3];
    const int*   item_ids = (const int*)  d_in[4];
    const float* emb      = (const float*)d_in[5];
    const float* W1       = (const float*)d_in[6];
    const float* a_l1     = (const float*)d_in[7];
    const float* a_r1     = (const float*)d_in[8];
    const float* b1       = (const float*)d_in[9];
    const float* W2       = (const float*)d_in[10];
    const float* a_l2     = (const float*)d_in[11];
    const float* a_r2     = (const float*)d_in[12];
    const float* b2       = (const float*)d_in[13];
    float* out = (float*)d_out;

    int *ulist, *ucount;
    __half *f1loc, *f2loc;
    float *el1, *er1, *h1loc, *el2, *er2, *h2loc;
    cudaGetSymbolAddress((void**)&ulist,  g_ulist);
    cudaGetSymbolAddress((void**)&ucount, g_ucount);
    cudaGetSymbolAddress((void**)&f1loc,  g_f1loc);
    cudaGetSymbolAddress((void**)&el1,    g_el1loc);
    cudaGetSymbolAddress((void**)&er1,    g_er1loc);
    cudaGetSymbolAddress((void**)&h1loc,  g_h1loc);
    cudaGetSymbolAddress((void**)&f2loc,  g_f2loc);
    cudaGetSymbolAddress((void**)&el2,    g_el2loc);
    cudaGetSymbolAddress((void**)&er2,    g_er2loc);
    cudaGetSymbolAddress((void**)&h2loc,  g_h2loc);

    // index construction (2 launches)
    init_kernel<<<(NND + 511)/512, 512>>>();
    mark_compact<<<(NS0 + 255)/256, 256>>>(src, feat_ids, user_ids, item_ids);

    // layer 1 GEMM over unique feat rows (dynamic count <= NS0)
    gemm_fused<64,256,32,4><<<(NS0 + 63)/64, 256>>>(
        emb, ulist, W1, a_l1, a_r1, f1loc, el1, er1, NS0, ucount, IN_F);
    agg1c_kernel<<<(NS1*32 + 255)/256, 256>>>(f1loc, el1, er1, b1, h1loc);

    // layer 2 GEMM over 2,176 local rows
    gemm_fused<64,64,32,1><<<NS1/64, 64>>>(
        h1loc, nullptr, W2, a_l2, a_r2, f2loc, el2, er2, NS1, nullptr, NH*HID);
    agg2c_kernel<<<(NT1*32)/256, 256>>>(f2loc, el2, er2, b2, h2loc);

    score_loss_kernel<<<1, 1024>>>(h2loc, out);
}

// round 13
// speedup vs baseline: 4.9385x; 1.7340x over previous
#include <cuda_runtime.h>

// ---------------- problem constants ----------------
#define NND   50000
#define DEG   16
#define IN_F  128
#define HID   64
#define NH    4
#define BATCH 64

#define NT1   128                 // targets = [uid(64), iid(64)]
#define NS1   (NT1*DEG + NT1)     // 2176 local nodes needing h1

typedef unsigned long long ull;

// ---------------- scratch ----------------
__device__ float g_wvec1[1024];        // wl1[4][128] | wr1[4][128]
__device__ float g_wvec2[512];         // wl2[256] | wr2[256]
__device__ float g_Z[NH*NS1*IN_F];     // head-major: [h][v][128]
__device__ float g_h1[NS1*NH*HID];     // [2176][256]
__device__ float g_h2[NT1*HID];        // [128][64]

// ---------------- packed f32x2 helpers ----------------
__device__ __forceinline__ ull pack_dup(float x) {
    ull r; asm("mov.b64 %0, {%1, %1};" : "=l"(r) : "f"(x)); return r;
}
__device__ __forceinline__ void ffma2(ull& acc, ull a, ull b) {
    asm("fma.rn.f32x2 %0, %1, %2, %0;" : "+l"(acc) : "l"(a), "l"(b));
}
__device__ __forceinline__ float2 unpack2(ull v) {
    float2 f; asm("mov.b64 {%0, %1}, %2;" : "=f"(f.x), "=f"(f.y) : "l"(v)); return f;
}
__device__ __forceinline__ float dot4(float4 a, float4 b) {
    return a.x*b.x + a.y*b.y + a.z*b.z + a.w*b.w;
}

// ---------------- K1: precompute attention projection vectors ----------------
__global__ void prep_kernel(const float* __restrict__ W1, const float* __restrict__ al1,
                            const float* __restrict__ ar1, const float* __restrict__ W2,
                            const float* __restrict__ al2, const float* __restrict__ ar2) {
    int t = threadIdx.x;   // 512 threads
    for (int id = t; id < 1024; id += 512) {
        int h = (id >> 7) & 3, k = id & 127;
        const float* av   = ((id >= 512) ? ar1 : al1) + h*HID;
        const float* wrow = W1 + (long)k*(NH*HID) + h*HID;
        float s = 0.f;
        #pragma unroll
        for (int q = 0; q < 16; q++)
            s += dot4(*(const float4*)(av + 4*q), *(const float4*)(wrow + 4*q));
        g_wvec1[id] = s;
    }
    {
        int id = t;   // 512 outputs, 512 threads
        int k = id & 255;
        const float* av   = (id < 256) ? al2 : ar2;
        const float* wrow = W2 + (long)k*HID;
        float s = 0.f;
        #pragma unroll
        for (int q = 0; q < 16; q++)
            s += dot4(*(const float4*)(av + 4*q), *(const float4*)(wrow + 4*q));
        g_wvec2[id] = s;
    }
}

// ---------------- K2: layer-1 attention + input-space aggregation ------------
// block = local node v; output z[h][v][128] = sum_e alpha_{e,h} * emb[fid_e]
__global__ __launch_bounds__(128)
void layer1_kernel(const int* __restrict__ src, const int* __restrict__ feat_ids,
                   const int* __restrict__ uid, const int* __restrict__ iid,
                   const float* __restrict__ emb, float* __restrict__ Z) {
    __shared__ float rows[17*132];
    __shared__ float wv[8*128];
    __shared__ int   fids[17];
    const int v = blockIdx.x;
    const int tid = threadIdx.x, lane = tid & 31, w = tid >> 5;

    // node u (uniform across block)
    int u;
    if (v < NT1*DEG) {
        int x = v >> 4;
        int t = (x < BATCH) ? uid[x] : iid[x - BATCH];
        u = src[t*DEG + (v & 15)];
    } else {
        int x = v - NT1*DEG;
        u = (x < BATCH) ? uid[x] : iid[x - BATCH];
    }
    if (tid < 16)       fids[tid] = feat_ids[src[u*DEG + tid]];
    else if (tid == 16) fids[16]  = feat_ids[u];
    __syncthreads();

    // stage 17 emb rows + wl1/wr1
    for (int idx = tid; idx < 17*32; idx += 128) {
        int r = idx >> 5, q = idx & 31;
        *(float4*)(rows + r*132 + q*4) =
            *(const float4*)(emb + (long)fids[r]*IN_F + q*4);
    }
    for (int idx = tid; idx < 256; idx += 128)
        *(float4*)(wv + idx*4) = *(const float4*)(g_wvec1 + idx*4);
    __syncthreads();

    // warp h: lanes 0..15 -> el dots, lane 16 -> er dot
    const int h = w;
    float acc = 0.f;
    {
        const float* wp = (lane < 16) ? (wv + h*128) : (wv + 512 + h*128);
        const float* rp = rows + (lane < 17 ? lane : 0)*132;
        if (lane < 17) {
            #pragma unroll
            for (int q = 0; q < 32; q++)
                acc += dot4(*(const float4*)(rp + 4*q), *(const float4*)(wp + 4*q));
        }
    }
    float er = __shfl_sync(~0u, acc, 16);
    float e  = acc + er;
    e = e > 0.f ? e : 0.2f * e;              // leaky_relu(0.2), lanes 0..15 valid
    float m = e;
    #pragma unroll
    for (int o = 8; o > 0; o >>= 1) m = fmaxf(m, __shfl_xor_sync(~0u, m, o, 16));
    float ex = __expf(e - m);
    float s = ex;
    #pragma unroll
    for (int o = 8; o > 0; o >>= 1) s += __shfl_xor_sync(~0u, s, o, 16);
    float alpha = ex / s;                    // lanes 0..15

    // z[h] : lane owns 4 dims
    float4 z = make_float4(0.f, 0.f, 0.f, 0.f);
    #pragma unroll
    for (int e2 = 0; e2 < 16; e2++) {
        float a = __shfl_sync(~0u, alpha, e2);
        float4 rv = *(const float4*)(rows + e2*132 + lane*4);
        z.x += a*rv.x; z.y += a*rv.y; z.z += a*rv.z; z.w += a*rv.w;
    }
    *(float4*)(Z + ((long)h*NS1 + v)*IN_F + lane*4) = z;
}

// ---------------- K3: h1 = relu(Z @ W1[:,hblk] + b1) -------------------------
// grid (34, 4): 64-row tile x head. 256 threads, thread tile 4x4 (FFMA2 row-pairs).
__global__ __launch_bounds__(256)
void gemm1b_kernel(const float* __restrict__ Z, const float* __restrict__ W1,
                   const float* __restrict__ b1, float* __restrict__ H1) {
    __shared__ float Zs[64][66];   // [k][row]
    __shared__ float Ws[64][64];   // [k][n]
    const int m0 = blockIdx.x * 64;
    const int h  = blockIdx.y;
    const int tid = threadIdx.x, lane = tid & 31, w = tid >> 5;
    const int wr = w & 3, wc = w >> 2;          // 4 row-groups x 2 col-groups
    const int lr = lane >> 3, lc = lane & 7;
    const int rbase = wr*16 + lr*4;             // 4 rows
    const int cbase = wc*32 + lc*4;             // 4 cols
    const float* Zh = Z + (long)h*NS1*IN_F;

    ull acc2[2][4];
    #pragma unroll
    for (int i = 0; i < 2; i++)
        #pragma unroll
        for (int j = 0; j < 4; j++) acc2[i][j] = 0ull;

    for (int k0 = 0; k0 < IN_F; k0 += 64) {
        for (int idx = tid; idx < 1024; idx += 256) {
            int r = idx >> 4, q = idx & 15;
            float4 vv = *(const float4*)(Zh + (long)(m0 + r)*IN_F + k0 + q*4);
            Zs[q*4+0][r] = vv.x; Zs[q*4+1][r] = vv.y;
            Zs[q*4+2][r] = vv.z; Zs[q*4+3][r] = vv.w;
        }
        for (int idx = tid; idx < 1024; idx += 256) {
            int k = idx >> 4, q = idx & 15;
            *(float4*)(&Ws[k][q*4]) =
                *(const float4*)(W1 + (long)(k0 + k)*(NH*HID) + h*HID + q*4);
        }
        __syncthreads();
        #pragma unroll 16
        for (int k = 0; k < 64; k++) {
            ull a0 = *(const ull*)(&Zs[k][rbase]);
            ull a1 = *(const ull*)(&Zs[k][rbase + 2]);
            float4 b4 = *(const float4*)(&Ws[k][cbase]);
            ull b0 = pack_dup(b4.x), bb1 = pack_dup(b4.y);
            ull b2 = pack_dup(b4.z), b3 = pack_dup(b4.w);
            ffma2(acc2[0][0], a0, b0); ffma2(acc2[0][1], a0, bb1);
            ffma2(acc2[0][2], a0, b2); ffma2(acc2[0][3], a0, b3);
            ffma2(acc2[1][0], a1, b0); ffma2(acc2[1][1], a1, bb1);
            ffma2(acc2[1][2], a1, b2); ffma2(acc2[1][3], a1, b3);
        }
        __syncthreads();
    }

    float4 bv = *(const float4*)(b1 + h*HID + cbase);
    #pragma unroll
    for (int p = 0; p < 2; p++) {
        float2 c0 = unpack2(acc2[p][0]);
        float2 c1 = unpack2(acc2[p][1]);
        float2 c2 = unpack2(acc2[p][2]);
        float2 c3 = unpack2(acc2[p][3]);
        int r0 = m0 + rbase + 2*p;
        float4 o0 = make_float4(fmaxf(c0.x + bv.x, 0.f), fmaxf(c1.x + bv.y, 0.f),
                                fmaxf(c2.x + bv.z, 0.f), fmaxf(c3.x + bv.w, 0.f));
        float4 o1 = make_float4(fmaxf(c0.y + bv.x, 0.f), fmaxf(c1.y + bv.y, 0.f),
                                fmaxf(c2.y + bv.z, 0.f), fmaxf(c3.y + bv.w, 0.f));
        *(float4*)(H1 + (long)r0*(NH*HID) + h*HID + cbase)       = o0;
        *(float4*)(H1 + (long)(r0 + 1)*(NH*HID) + h*HID + cbase) = o1;
    }
}

// ---------------- K4: layer-2 attention + aggregation + GEMM2 + bias ---------
// block = target i (128 blocks, 256 threads); h2[i] = (sum_e alpha h1[src]) @ W2 + b2
__global__ __launch_bounds__(256)
void layer2_kernel(const float* __restrict__ H1, const float* __restrict__ W2,
                   const float* __restrict__ b2, float* __restrict__ h2) {
    __shared__ float rows[17*260];
    __shared__ float wv[512];
    __shared__ float alpha_sm[16];
    __shared__ float z2[256];
    __shared__ float part[4][64];
    const int i = blockIdx.x;
    const int tid = threadIdx.x, lane = tid & 31, w = tid >> 5;

    for (int idx = tid; idx < 17*64; idx += 256) {
        int r = idx >> 6, q = idx & 63;
        int grow = (r < 16) ? (i*DEG + r) : (NT1*DEG + i);
        *(float4*)(rows + r*260 + q*4) =
            *(const float4*)(H1 + (long)grow*(NH*HID) + q*4);
    }
    for (int idx = tid; idx < 128; idx += 256)
        *(float4*)(wv + idx*4) = *(const float4*)(g_wvec2 + idx*4);
    __syncthreads();

    if (w == 0) {
        float acc = 0.f;
        const float* wp = (lane < 16) ? wv : (wv + 256);
        const float* rp = rows + (lane < 17 ? lane : 0)*260;
        if (lane < 17) {
            #pragma unroll
            for (int q = 0; q < 64; q++)
                acc += dot4(*(const float4*)(rp + 4*q), *(const float4*)(wp + 4*q));
        }
        float er = __shfl_sync(~0u, acc, 16);
        float e  = acc + er;
        e = e > 0.f ? e : 0.2f * e;
        float m = e;
        #pragma unroll
        for (int o = 8; o > 0; o >>= 1) m = fmaxf(m, __shfl_xor_sync(~0u, m, o, 16));
        float ex = __expf(e - m);
        float s = ex;
        #pragma unroll
        for (int o = 8; o > 0; o >>= 1) s += __shfl_xor_sync(~0u, s, o, 16);
        if (lane < 16) alpha_sm[lane] = ex / s;
    }
    __syncthreads();

    float z = 0.f;
    #pragma unroll
    for (int e = 0; e < 16; e++) z += alpha_sm[e] * rows[e*260 + tid];
    z2[tid] = z;
    __syncthreads();

    // GEMM: n = tid&63, k-quarter = tid>>6
    const int n = tid & 63, kh = tid >> 6;
    float acc = 0.f;
    #pragma unroll
    for (int k = 0; k < 64; k++)
        acc += z2[kh*64 + k] * W2[(long)(kh*64 + k)*HID + n];
    part[kh][n] = acc;
    __syncthreads();
    if (tid < 64)
        h2[(long)i*HID + tid] =
            part[0][tid] + part[1][tid] + part[2][tid] + part[3][tid] + b2[tid];
}

// ------- K5: fused scores + labels + per-row loss + mean (single block) ------
__global__ __launch_bounds__(1024)
void score_loss_kernel(const float* __restrict__ h2loc, float* __restrict__ out) {
    int lane = threadIdx.x & 31, warp = threadIdx.x >> 5;
    __shared__ float sloss[BATCH];
    #pragma unroll
    for (int rep = 0; rep < 2; rep++) {
        int i = warp*2 + rep;
        float su0 = h2loc[i*HID + lane];
        float su1 = h2loc[i*HID + lane + 32];
        float si0 = h2loc[(BATCH + i)*HID + lane];
        float si1 = h2loc[(BATCH + i)*HID + lane + 32];
        float sc0 = su0*si0, sc1 = su1*si1;
        out[1 + i*BATCH + lane]      = sc0;
        out[1 + i*BATCH + lane + 32] = sc1;
        out[1 + BATCH*BATCH + i*BATCH + lane]      = (i == lane)      ? 1.f : 0.f;
        out[1 + BATCH*BATCH + i*BATCH + lane + 32] = (i == lane + 32) ? 1.f : 0.f;
        float diag = (i < 32) ? __shfl_sync(~0u, sc0, i)
                              : __shfl_sync(~0u, sc1, i - 32);
        float m = fmaxf(sc0, sc1);
        #pragma unroll
        for (int o = 16; o; o >>= 1) m = fmaxf(m, __shfl_xor_sync(~0u, m, o));
        float s = expf(sc0 - m) + expf(sc1 - m);
        #pragma unroll
        for (int o = 16; o; o >>= 1) s += __shfl_xor_sync(~0u, s, o);
        if (lane == 0) sloss[i] = m + logf(s) - diag;
    }
    __syncthreads();
    if (warp == 0) {
        float s = sloss[lane] + sloss[lane + 32];
        #pragma unroll
        for (int o = 16; o; o >>= 1) s += __shfl_xor_sync(~0u, s, o);
        if (lane == 0) out[0] = s / (float)BATCH;
    }
}

// ---------------- launcher ----------------
extern "C" void kernel_launch(void* const* d_in, const int* in_sizes, int n_in,
                              void* d_out, int out_size) {
    const int*   feat_ids = (const int*)  d_in[0];
    const int*   src      = (const int*)  d_in[1];
    const int*   user_ids = (const int*)  d_in[3];
    const int*   item_ids = (const int*)  d_in[4];
    const float* emb      = (const float*)d_in[5];
    const float* W1       = (const float*)d_in[6];
    const float* a_l1     = (const float*)d_in[7];
    const float* a_r1     = (const float*)d_in[8];
    const float* b1       = (const float*)d_in[9];
    const float* W2       = (const float*)d_in[10];
    const float* a_l2     = (const float*)d_in[11];
    const float* a_r2     = (const float*)d_in[12];
    const float* b2       = (const float*)d_in[13];
    float* out = (float*)d_out;

    float *Z, *h1, *h2;
    cudaGetSymbolAddress((void**)&Z,  g_Z);
    cudaGetSymbolAddress((void**)&h1, g_h1);
    cudaGetSymbolAddress((void**)&h2, g_h2);

    prep_kernel<<<1, 512>>>(W1, a_l1, a_r1, W2, a_l2, a_r2);
    layer1_kernel<<<NS1, 128>>>(src, feat_ids, user_ids, item_ids, emb, Z);
    gemm1b_kernel<<<dim3(NS1/64, NH), 256>>>(Z, W1, b1, h1);
    layer2_kernel<<<NT1, 256>>>(h1, W2, b2, h2);
    score_loss_kernel<<<1, 1024>>>(h2, out);
}

// round 14
// speedup vs baseline: 5.7236x; 1.1590x over previous
#include <cuda_runtime.h>

// ---------------- problem constants ----------------
#define NND   50000
#define DEG   16
#define IN_F  128
#define HID   64
#define NH    4
#define BATCH 64

#define NT1   128                 // targets = [uid(64), iid(64)]
#define NS1   (NT1*DEG + NT1)     // 2176 local nodes needing h1

typedef unsigned long long ull;

// ---------------- scratch ----------------
__device__ float g_wvec1[1024];        // wl1[4][128] | wr1[4][128]
__device__ float g_wvec2[512];         // wl2[256] | wr2[256]
__device__ float g_Z[NH*NS1*IN_F];     // head-major: [h][v][128]
__device__ float g_h1[NS1*NH*HID];     // [2176][256]
__device__ float g_h2[NT1*HID];        // [128][64]
__device__ int   g_done;               // layer2 completion ticket

// ---------------- packed f32x2 helpers ----------------
__device__ __forceinline__ ull pack_dup(float x) {
    ull r; asm("mov.b64 %0, {%1, %1};" : "=l"(r) : "f"(x)); return r;
}
__device__ __forceinline__ void ffma2(ull& acc, ull a, ull b) {
    asm("fma.rn.f32x2 %0, %1, %2, %0;" : "+l"(acc) : "l"(a), "l"(b));
}
__device__ __forceinline__ float2 unpack2(ull v) {
    float2 f; asm("mov.b64 {%0, %1}, %2;" : "=f"(f.x), "=f"(f.y) : "l"(v)); return f;
}
__device__ __forceinline__ float dot4(float4 a, float4 b) {
    return a.x*b.x + a.y*b.y + a.z*b.z + a.w*b.w;
}

// ---------------- K1: attention projection vectors (6 blocks) ----------------
__global__ void prep_kernel(const float* __restrict__ W1, const float* __restrict__ al1,
                            const float* __restrict__ ar1, const float* __restrict__ W2,
                            const float* __restrict__ al2, const float* __restrict__ ar2) {
    int id = blockIdx.x*256 + threadIdx.x;     // 0..1535
    if (id == 0) g_done = 0;                   // reset ticket every replay
    if (id < 1024) {
        int h = (id >> 7) & 3, k = id & 127;
        const float* av   = ((id >= 512) ? ar1 : al1) + h*HID;
        const float* wrow = W1 + (long)k*(NH*HID) + h*HID;
        float s = 0.f;
        #pragma unroll
        for (int q = 0; q < 16; q++)
            s += dot4(*(const float4*)(av + 4*q), *(const float4*)(wrow + 4*q));
        g_wvec1[id] = s;
    } else {
        int id2 = id - 1024;                   // 0..511
        int k = id2 & 255;
        const float* av   = (id2 < 256) ? al2 : ar2;
        const float* wrow = W2 + (long)k*HID;
        float s = 0.f;
        #pragma unroll
        for (int q = 0; q < 16; q++)
            s += dot4(*(const float4*)(av + 4*q), *(const float4*)(wrow + 4*q));
        g_wvec2[id2] = s;
    }
}

// ---------------- K2: layer-1 attention + input-space aggregation ------------
__global__ __launch_bounds__(128)
void layer1_kernel(const int* __restrict__ src, const int* __restrict__ feat_ids,
                   const int* __restrict__ uid, const int* __restrict__ iid,
                   const float* __restrict__ emb, float* __restrict__ Z) {
    __shared__ float rows[17*132];
    __shared__ float wv[8*128];
    __shared__ int   fids[17];
    const int v = blockIdx.x;
    const int tid = threadIdx.x, lane = tid & 31, w = tid >> 5;

    int u;
    if (v < NT1*DEG) {
        int x = v >> 4;
        int t = (x < BATCH) ? uid[x] : iid[x - BATCH];
        u = src[t*DEG + (v & 15)];
    } else {
        int x = v - NT1*DEG;
        u = (x < BATCH) ? uid[x] : iid[x - BATCH];
    }
    if (tid < 16)       fids[tid] = feat_ids[src[u*DEG + tid]];
    else if (tid == 16) fids[16]  = feat_ids[u];
    __syncthreads();

    for (int idx = tid; idx < 17*32; idx += 128) {
        int r = idx >> 5, q = idx & 31;
        *(float4*)(rows + r*132 + q*4) =
            *(const float4*)(emb + (long)fids[r]*IN_F + q*4);
    }
    for (int idx = tid; idx < 256; idx += 128)
        *(float4*)(wv + idx*4) = *(const float4*)(g_wvec1 + idx*4);
    __syncthreads();

    const int h = w;
    float acc = 0.f;
    {
        const float* wp = (lane < 16) ? (wv + h*128) : (wv + 512 + h*128);
        const float* rp = rows + (lane < 17 ? lane : 0)*132;
        if (lane < 17) {
            #pragma unroll
            for (int q = 0; q < 32; q++)
                acc += dot4(*(const float4*)(rp + 4*q), *(const float4*)(wp + 4*q));
        }
    }
    float er = __shfl_sync(~0u, acc, 16);
    float e  = acc + er;
    e = e > 0.f ? e : 0.2f * e;
    float m = e;
    #pragma unroll
    for (int o = 8; o > 0; o >>= 1) m = fmaxf(m, __shfl_xor_sync(~0u, m, o, 16));
    float ex = __expf(e - m);
    float s = ex;
    #pragma unroll
    for (int o = 8; o > 0; o >>= 1) s += __shfl_xor_sync(~0u, s, o, 16);
    float alpha = ex / s;

    float4 z = make_float4(0.f, 0.f, 0.f, 0.f);
    #pragma unroll
    for (int e2 = 0; e2 < 16; e2++) {
        float a = __shfl_sync(~0u, alpha, e2);
        float4 rv = *(const float4*)(rows + e2*132 + lane*4);
        z.x += a*rv.x; z.y += a*rv.y; z.z += a*rv.z; z.w += a*rv.w;
    }
    *(float4*)(Z + ((long)h*NS1 + v)*IN_F + lane*4) = z;
}

// ---------------- K3: h1 = relu(Z @ W1[:,hblk] + b1) -------------------------
__global__ __launch_bounds__(256)
void gemm1b_kernel(const float* __restrict__ Z, const float* __restrict__ W1,
                   const float* __restrict__ b1, float* __restrict__ H1) {
    __shared__ float Zs[64][66];
    __shared__ float Ws[64][64];
    const int m0 = blockIdx.x * 64;
    const int h  = blockIdx.y;
    const int tid = threadIdx.x, lane = tid & 31, w = tid >> 5;
    const int wr = w & 3, wc = w >> 2;
    const int lr = lane >> 3, lc = lane & 7;
    const int rbase = wr*16 + lr*4;
    const int cbase = wc*32 + lc*4;
    const float* Zh = Z + (long)h*NS1*IN_F;

    ull acc2[2][4];
    #pragma unroll
    for (int i = 0; i < 2; i++)
        #pragma unroll
        for (int j = 0; j < 4; j++) acc2[i][j] = 0ull;

    for (int k0 = 0; k0 < IN_F; k0 += 64) {
        for (int idx = tid; idx < 1024; idx += 256) {
            int r = idx >> 4, q = idx & 15;
            float4 vv = *(const float4*)(Zh + (long)(m0 + r)*IN_F + k0 + q*4);
            Zs[q*4+0][r] = vv.x; Zs[q*4+1][r] = vv.y;
            Zs[q*4+2][r] = vv.z; Zs[q*4+3][r] = vv.w;
        }
        for (int idx = tid; idx < 1024; idx += 256) {
            int k = idx >> 4, q = idx & 15;
            *(float4*)(&Ws[k][q*4]) =
                *(const float4*)(W1 + (long)(k0 + k)*(NH*HID) + h*HID + q*4);
        }
        __syncthreads();
        #pragma unroll 16
        for (int k = 0; k < 64; k++) {
            ull a0 = *(const ull*)(&Zs[k][rbase]);
            ull a1 = *(const ull*)(&Zs[k][rbase + 2]);
            float4 b4 = *(const float4*)(&Ws[k][cbase]);
            ull b0 = pack_dup(b4.x), bb1 = pack_dup(b4.y);
            ull b2 = pack_dup(b4.z), b3 = pack_dup(b4.w);
            ffma2(acc2[0][0], a0, b0); ffma2(acc2[0][1], a0, bb1);
            ffma2(acc2[0][2], a0, b2); ffma2(acc2[0][3], a0, b3);
            ffma2(acc2[1][0], a1, b0); ffma2(acc2[1][1], a1, bb1);
            ffma2(acc2[1][2], a1, b2); ffma2(acc2[1][3], a1, b3);
        }
        __syncthreads();
    }

    float4 bv = *(const float4*)(b1 + h*HID + cbase);
    #pragma unroll
    for (int p = 0; p < 2; p++) {
        float2 c0 = unpack2(acc2[p][0]);
        float2 c1 = unpack2(acc2[p][1]);
        float2 c2 = unpack2(acc2[p][2]);
        float2 c3 = unpack2(acc2[p][3]);
        int r0 = m0 + rbase + 2*p;
        float4 o0 = make_float4(fmaxf(c0.x + bv.x, 0.f), fmaxf(c1.x + bv.y, 0.f),
                                fmaxf(c2.x + bv.z, 0.f), fmaxf(c3.x + bv.w, 0.f));
        float4 o1 = make_float4(fmaxf(c0.y + bv.x, 0.f), fmaxf(c1.y + bv.y, 0.f),
                                fmaxf(c2.y + bv.z, 0.f), fmaxf(c3.y + bv.w, 0.f));
        *(float4*)(H1 + (long)r0*(NH*HID) + h*HID + cbase)       = o0;
        *(float4*)(H1 + (long)(r0 + 1)*(NH*HID) + h*HID + cbase) = o1;
    }
}

// --------- K4: layer-2 attention + agg + GEMM2 + bias + FUSED score ----------
__global__ __launch_bounds__(256)
void layer2_kernel(const float* __restrict__ H1, const float* __restrict__ W2,
                   const float* __restrict__ b2, float* __restrict__ h2,
                   float* __restrict__ out) {
    __shared__ float rows[17*260];
    __shared__ float wv[512];
    __shared__ float dots_sm[17];
    __shared__ float alpha_sm[16];
    __shared__ float z2[256];
    __shared__ float part[4][64];
    __shared__ int   ticket_sm;
    const int i = blockIdx.x;
    const int tid = threadIdx.x, lane = tid & 31, w = tid >> 5;

    for (int idx = tid; idx < 17*64; idx += 256) {
        int r = idx >> 6, q = idx & 63;
        int grow = (r < 16) ? (i*DEG + r) : (NT1*DEG + i);
        *(float4*)(rows + r*260 + q*4) =
            *(const float4*)(H1 + (long)grow*(NH*HID) + q*4);
    }
    for (int idx = tid; idx < 128; idx += 256)
        *(float4*)(wv + idx*4) = *(const float4*)(g_wvec2 + idx*4);
    __syncthreads();

    // 17 dots, warp-parallel with shuffle-tree reduce
    for (int d = w; d < 17; d += 8) {
        const float* wp = ((d < 16) ? wv : (wv + 256)) + lane*8;
        const float* rp = rows + d*260 + lane*8;
        float p = dot4(*(const float4*)rp,     *(const float4*)wp)
                + dot4(*(const float4*)(rp+4), *(const float4*)(wp+4));
        #pragma unroll
        for (int o = 16; o; o >>= 1) p += __shfl_xor_sync(~0u, p, o);
        if (lane == 0) dots_sm[d] = p;
    }
    __syncthreads();

    if (w == 0 && lane < 16) {
        float e = dots_sm[lane] + dots_sm[16];
        e = e > 0.f ? e : 0.2f * e;
        float m = e;
        #pragma unroll
        for (int o = 8; o > 0; o >>= 1) m = fmaxf(m, __shfl_xor_sync(0xFFFFu, m, o, 16));
        float ex = __expf(e - m);
        float s = ex;
        #pragma unroll
        for (int o = 8; o > 0; o >>= 1) s += __shfl_xor_sync(0xFFFFu, s, o, 16);
        alpha_sm[lane] = ex / s;
    }
    __syncthreads();

    float za = 0.f, zb = 0.f;
    #pragma unroll
    for (int e = 0; e < 16; e += 2) {
        za += alpha_sm[e]   * rows[e*260 + tid];
        zb += alpha_sm[e+1] * rows[(e+1)*260 + tid];
    }
    z2[tid] = za + zb;
    __syncthreads();

    const int n = tid & 63, kh = tid >> 6;
    float a0=0.f, a1=0.f, a2=0.f, a3=0.f;
    #pragma unroll
    for (int k = 0; k < 64; k += 4) {
        a0 += z2[kh*64+k]   * W2[(long)(kh*64+k)*HID + n];
        a1 += z2[kh*64+k+1] * W2[(long)(kh*64+k+1)*HID + n];
        a2 += z2[kh*64+k+2] * W2[(long)(kh*64+k+2)*HID + n];
        a3 += z2[kh*64+k+3] * W2[(long)(kh*64+k+3)*HID + n];
    }
    part[kh][n] = (a0 + a1) + (a2 + a3);
    __syncthreads();
    if (tid < 64)
        h2[(long)i*HID + tid] =
            part[0][tid] + part[1][tid] + part[2][tid] + part[3][tid] + b2[tid];

    // ---- last-block score+loss (threadfence + ticket) ----
    __threadfence();
    __syncthreads();
    if (tid == 0) ticket_sm = atomicAdd(&g_done, 1);
    __syncthreads();
    if (ticket_sm != NT1 - 1) return;
    __threadfence();

    __shared__ float sloss[BATCH];
    const float* h2r = h2;
    for (int r = 0; r < 8; r++) {
        int row = w*8 + r;
        float su0 = h2r[row*HID + lane];
        float su1 = h2r[row*HID + lane + 32];
        float si0 = h2r[(BATCH + row)*HID + lane];
        float si1 = h2r[(BATCH + row)*HID + lane + 32];
        float sc0 = su0*si0, sc1 = su1*si1;
        out[1 + row*BATCH + lane]      = sc0;
        out[1 + row*BATCH + lane + 32] = sc1;
        out[1 + BATCH*BATCH + row*BATCH + lane]      = (row == lane)      ? 1.f : 0.f;
        out[1 + BATCH*BATCH + row*BATCH + lane + 32] = (row == lane + 32) ? 1.f : 0.f;
        float diag = (row < 32) ? __shfl_sync(~0u, sc0, row)
                                : __shfl_sync(~0u, sc1, row - 32);
        float m = fmaxf(sc0, sc1);
        #pragma unroll
        for (int o = 16; o; o >>= 1) m = fmaxf(m, __shfl_xor_sync(~0u, m, o));
        float s = expf(sc0 - m) + expf(sc1 - m);
        #pragma unroll
        for (int o = 16; o; o >>= 1) s += __shfl_xor_sync(~0u, s, o);
        if (lane == 0) sloss[row] = m + logf(s) - diag;
    }
    __syncthreads();
    if (w == 0) {
        float s = sloss[lane] + sloss[lane + 32];
        #pragma unroll
        for (int o = 16; o; o >>= 1) s += __shfl_xor_sync(~0u, s, o);
        if (lane == 0) out[0] = s / (float)BATCH;
    }
}

// ---------------- launcher ----------------
extern "C" void kernel_launch(void* const* d_in, const int* in_sizes, int n_in,
                              void* d_out, int out_size) {
    const int*   feat_ids = (const int*)  d_in[0];
    const int*   src      = (const int*)  d_in[1];
    const int*   user_ids = (const int*)  d_in[3];
    const int*   item_ids = (const int*)  d_in[4];
    const float* emb      = (const float*)d_in[5];
    const float* W1       = (const float*)d_in[6];
    const float* a_l1     = (const float*)d_in[7];
    const float* a_r1     = (const float*)d_in[8];
    const float* b1       = (const float*)d_in[9];
    const float* W2       = (const float*)d_in[10];
    const float* a_l2     = (const float*)d_in[11];
    const float* a_r2     = (const float*)d_in[12];
    const float* b2       = (const float*)d_in[13];
    float* out = (float*)d_out;

    float *Z, *h1, *h2;
    cudaGetSymbolAddress((void**)&Z,  g_Z);
    cudaGetSymbolAddress((void**)&h1, g_h1);
    cudaGetSymbolAddress((void**)&h2, g_h2);

    prep_kernel<<<6, 256>>>(W1, a_l1, a_r1, W2, a_l2, a_r2);
    layer1_kernel<<<NS1, 128>>>(src, feat_ids, user_ids, item_ids, emb, Z);
    gemm1b_kernel<<<dim3(NS1/64, NH), 256>>>(Z, W1, b1, h1);
    layer2_kernel<<<NT1, 256>>>(h1, W2, b2, h2, out);
}